// round 13
// baseline (speedup 1.0000x reference)
#include <cuda_runtime.h>
#include <cuda_fp16.h>
#include <cstdint>

#define BATCH 8
#define SEQ   2048
#define EMBD  1024
#define OUTD  1024

// Scratch (device globals; allocations are forbidden)
__device__ __align__(256) __half g_et[(size_t)BATCH * SEQ * EMBD];  // fp16 embd 32MB
__device__ __align__(256) __half g_wt[(size_t)OUTD * EMBD];         // fp16 W     2MB
__device__ __align__(256) __half g_c [(size_t)BATCH * SEQ * OUTD];  // c fp16    32MB
__device__ __align__(256) __half g_ct[(size_t)BATCH * OUTD * SEQ];  // c^T fp16  32MB
__device__ __align__(256) float  g_s [(size_t)BATCH * SEQ * SEQ];   // scores   128MB
__device__ __align__(256) __half g_p [(size_t)BATCH * SEQ * SEQ];   // probs*1024 64MB

// ---------------------------------------------------------------------------
__device__ __forceinline__ uint32_t smem_u32(const void* p) {
    uint32_t a;
    asm("{ .reg .u64 t; cvta.to.shared.u64 t, %1; cvt.u32.u64 %0, t; }"
        : "=r"(a) : "l"(p));
    return a;
}
__device__ __forceinline__ void sts_f(uint32_t a, float v) {
    asm volatile("st.shared.b32 [%0], %1;" :: "r"(a), "f"(v) : "memory");
}
__device__ __forceinline__ float4 lds_f4(uint32_t a) {
    float4 v;
    asm volatile("ld.shared.v4.f32 {%0,%1,%2,%3}, [%4];"
                 : "=f"(v.x), "=f"(v.y), "=f"(v.z), "=f"(v.w) : "r"(a));
    return v;
}
__device__ __forceinline__ void ldsm4(uint32_t addr, uint32_t& r0, uint32_t& r1,
                                      uint32_t& r2, uint32_t& r3) {
    asm volatile("ldmatrix.sync.aligned.m8n8.x4.shared.b16 {%0,%1,%2,%3}, [%4];"
                 : "=r"(r0), "=r"(r1), "=r"(r2), "=r"(r3) : "r"(addr));
}
// fp16 MMA, fp32 accumulate: m16n8k16
__device__ __forceinline__ void mma_f16(float c[4], uint32_t a0, uint32_t a1,
                                        uint32_t a2, uint32_t a3,
                                        uint32_t b0, uint32_t b1) {
    asm volatile(
        "mma.sync.aligned.m16n8k16.row.col.f32.f16.f16.f32 "
        "{%0,%1,%2,%3}, {%4,%5,%6,%7}, {%8,%9}, {%0,%1,%2,%3};"
        : "+f"(c[0]), "+f"(c[1]), "+f"(c[2]), "+f"(c[3])
        : "r"(a0), "r"(a1), "r"(a2), "r"(a3), "r"(b0), "r"(b1));
}
__device__ __forceinline__ uint32_t sw128(uint32_t bo) {
    return bo ^ ((bo >> 3) & 0x70);
}

// ---------------------------------------------------------------------------
// fp16 mma.sync GEMM (all NT): 128x128 CTA tile, BK=64, 4 warps, warp 64x64.
// 128 threads, 2 CTAs/SM.  (R9 champion configuration)
// MODE 0: +bias, write C fp16 AND C^T fp16                (GEMM1)
// MODE 1: *alpha, write C fp32                             (GEMM3)
// MODE 3: *alpha, fp32, SYMMETRIC triangular + mirror      (GEMM2)
// ---------------------------------------------------------------------------
#define STG     3
#define A_TB    16384                    // 128 rows x 128B
#define SB_OFF  (STG * A_TB)             // 49152
#define B_TB    16384
#define DSMEM   (SB_OFF + STG * B_TB + 1024)
#define TPITCH  132                      // transpose staging pitch (floats)

template <int MODE>
__global__ __launch_bounds__(128, 2)
void tc_gemm(const __half* __restrict__ Ag, const __half* __restrict__ Bg,
             const float* __restrict__ bias,
             float* __restrict__ Cg,            // fp32 out (MODE 1,3)
             __half* __restrict__ Ch,           // fp16 out (MODE 0)
             __half* __restrict__ CTg,          // fp16 transposed out (MODE 0)
             int N, int K, float alpha,
             size_t strA, size_t strB, size_t strC)
{
    extern __shared__ char dsm[];
    const uint32_t sb = (smem_u32(dsm) + 1023u) & ~1023u;

    Ag += (size_t)blockIdx.z * strA;
    Bg += (size_t)blockIdx.z * strB;
    if (MODE != 0) Cg += (size_t)blockIdx.z * strC;

    const int tid  = threadIdx.x;
    const int lane = tid & 31;
    const int wid  = tid >> 5;           // 0..3
    const int wm0  = (wid & 1) * 64;     // warp m offset
    const int wn0  = (wid >> 1) * 64;    // warp n offset

    int row0, col0;
    if (MODE == 3) {
        const int t = blockIdx.x;
        int r = (int)((sqrtf(8.0f * (float)t + 1.0f) - 1.0f) * 0.5f);
        while ((r + 1) * (r + 2) / 2 <= t) r++;
        while (r * (r + 1) / 2 > t)        r--;
        const int cc = t - r * (r + 1) / 2;
        row0 = r  * 128;
        col0 = cc * 128;
    } else {
        row0 = blockIdx.y * 128;
        col0 = blockIdx.x * 128;
    }

    const int NCH = K >> 6;              // BK = 64 fp16
    const int q = lane >> 2;             // 0..7 (fragment row)
    const int s = lane & 3;              // 0..3

    // ldmatrix per-lane constants
    const uint32_t tb   = ((lane >> 3) & 1) << 3;   // +8 rows for odd tiles
    const uint32_t th16 = ((lane >> 4) & 1) << 4;   // +16B => k 8..15
    const uint32_t xr   = (uint32_t)(lane & 7) << 4;
    uint32_t roffA[4], roffB[4];
#pragma unroll
    for (int t4 = 0; t4 < 4; t4++) {
        roffA[t4] = (uint32_t)(wm0 + (t4 << 4) + tb + (lane & 7)) << 7;
        roffB[t4] = (uint32_t)(wn0 + (t4 << 4) + tb + (lane & 7)) << 7;
    }

    float acc[4][8][4];
#pragma unroll
    for (int i = 0; i < 4; i++)
#pragma unroll
        for (int j = 0; j < 8; j++)
#pragma unroll
            for (int r = 0; r < 4; r++) acc[i][j][r] = 0.f;

    auto issue = [&](int ch, int st) {
        const int k0 = ch << 6;                    // fp16 elements
#pragma unroll
        for (int i = 0; i < 16; i++) {
            int g   = tid + (i << 7);              // 0..2047
            int isB = g >> 10;
            int gl  = g & 1023;
            int r   = gl >> 3;                     // row 0..127
            int gg  = gl & 7;                      // 16B granule (8 fp16)
            const __half* src = (isB ? Bg + (size_t)(col0 + r) * K
                                     : Ag + (size_t)(row0 + r) * K) + k0 + (gg << 3);
            uint32_t dst = sb + (isB ? SB_OFF : 0) + st * B_TB
                         + sw128((r << 7) + (gg << 4));
            asm volatile("cp.async.cg.shared.global [%0], [%1], 16;"
                         :: "r"(dst), "l"(src) : "memory");
        }
        asm volatile("cp.async.commit_group;" ::: "memory");
    };

    auto step = [&](int ch, const int st) {
        asm volatile("cp.async.wait_group 1;" ::: "memory");
        __syncthreads();
        if (ch + 2 < NCH) issue(ch + 2, (st + 2) % STG);
        else asm volatile("cp.async.commit_group;" ::: "memory");

        const uint32_t ab = sb + st * A_TB;
        const uint32_t bb = sb + SB_OFF + st * B_TB;

#pragma unroll
        for (int ks = 0; ks < 4; ks++) {           // 4 x k16 = BK 64
            const uint32_t kx = (((uint32_t)ks << 5) + th16) ^ xr;
            uint32_t af[16], bf[16];
#pragma unroll
            for (int tp = 0; tp < 4; tp++) {
                ldsm4(bb + roffB[tp] + kx,
                      bf[(tp * 2) * 2], bf[(tp * 2 + 1) * 2],
                      bf[(tp * 2) * 2 + 1], bf[(tp * 2 + 1) * 2 + 1]);
            }
#pragma unroll
            for (int tm = 0; tm < 4; tm++)
                ldsm4(ab + roffA[tm] + kx,
                      af[tm * 4], af[tm * 4 + 1], af[tm * 4 + 2], af[tm * 4 + 3]);
#pragma unroll
            for (int tm = 0; tm < 4; tm++)
#pragma unroll
                for (int tn = 0; tn < 8; tn++)
                    mma_f16(acc[tm][tn], af[tm * 4], af[tm * 4 + 1],
                            af[tm * 4 + 2], af[tm * 4 + 3],
                            bf[tn * 2], bf[tn * 2 + 1]);
        }
    };

    issue(0, 0);
    issue(1, 1);

    int ch = 0;
#pragma unroll 1
    for (; ch + 3 <= NCH; ch += 3) {
        step(ch,     0);
        step(ch + 1, 1);
        step(ch + 2, 2);
    }
    if (ch < NCH) { step(ch, 0); ch++; }
    if (ch < NCH) { step(ch, 1); }

    // -------- epilogue --------
    if (MODE == 0) {
        // bias add, round to fp16, write C (fp16) and stage for C^T
#pragma unroll
        for (int tm = 0; tm < 4; tm++) {
            const size_t r_lo = (size_t)row0 + wm0 + (tm << 4) + q;
#pragma unroll
            for (int tn = 0; tn < 8; tn++) {
                const int col = col0 + wn0 + (tn << 3) + (s << 1);
                const float b0 = __ldg(bias + col), b1 = __ldg(bias + col + 1);
                __half h0 = __float2half_rn(acc[tm][tn][0] + b0);
                __half h1 = __float2half_rn(acc[tm][tn][1] + b1);
                __half h2 = __float2half_rn(acc[tm][tn][2] + b0);
                __half h3 = __float2half_rn(acc[tm][tn][3] + b1);
                acc[tm][tn][0] = __half2float(h0);
                acc[tm][tn][1] = __half2float(h1);
                acc[tm][tn][2] = __half2float(h2);
                acc[tm][tn][3] = __half2float(h3);
                *reinterpret_cast<__half2*>(Ch + r_lo * N + col) =
                    __halves2half2(h0, h1);
                *reinterpret_cast<__half2*>(Ch + (r_lo + 8) * N + col) =
                    __halves2half2(h2, h3);
            }
        }
        // transpose-stage fp32 in smem, write C^T fp16 coalesced
        asm volatile("cp.async.wait_group 0;" ::: "memory");
        __syncthreads();
#pragma unroll
        for (int tm = 0; tm < 4; tm++) {
            const int m = wm0 + (tm << 4) + q;
#pragma unroll
            for (int tn = 0; tn < 8; tn++) {
                const int n = wn0 + (tn << 3) + (s << 1);
                sts_f(sb + (uint32_t)(n       * TPITCH + m)     * 4, acc[tm][tn][0]);
                sts_f(sb + (uint32_t)((n + 1) * TPITCH + m)     * 4, acc[tm][tn][1]);
                sts_f(sb + (uint32_t)(n       * TPITCH + m + 8) * 4, acc[tm][tn][2]);
                sts_f(sb + (uint32_t)((n + 1) * TPITCH + m + 8) * 4, acc[tm][tn][3]);
            }
        }
        __syncthreads();
        const int b  = row0 >> 11;           // batch (rows are batch-major)
        const int m2 = row0 & 2047;
        __half* dstrow = CTg + (size_t)b * OUTD * SEQ + (size_t)(col0 + tid) * SEQ + m2;
        const uint32_t srow = sb + (uint32_t)(tid * TPITCH) * 4;
#pragma unroll
        for (int j = 0; j < 128; j += 4) {
            float4 v = lds_f4(srow + j * 4);
            *reinterpret_cast<__half2*>(dstrow + j)     = __floats2half2_rn(v.x, v.y);
            *reinterpret_cast<__half2*>(dstrow + j + 2) = __floats2half2_rn(v.z, v.w);
        }
    } else if (MODE == 1) {
#pragma unroll
        for (int tm = 0; tm < 4; tm++) {
            const size_t r_lo = (size_t)row0 + wm0 + (tm << 4) + q;
#pragma unroll
            for (int tn = 0; tn < 8; tn++) {
                const int col = col0 + wn0 + (tn << 3) + (s << 1);
                *reinterpret_cast<float2*>(Cg + r_lo * N + col) =
                    make_float2(acc[tm][tn][0] * alpha, acc[tm][tn][1] * alpha);
                *reinterpret_cast<float2*>(Cg + (r_lo + 8) * N + col) =
                    make_float2(acc[tm][tn][2] * alpha, acc[tm][tn][3] * alpha);
            }
        }
    } else {  // MODE 3
        const bool diag = (row0 == col0);
#pragma unroll
        for (int tm = 0; tm < 4; tm++) {
            const size_t r_lo = (size_t)row0 + wm0 + (tm << 4) + q;
#pragma unroll
            for (int tn = 0; tn < 8; tn++) {
                const int col = col0 + wn0 + (tn << 3) + (s << 1);
                float v0 = acc[tm][tn][0] * alpha, v1 = acc[tm][tn][1] * alpha;
                float v2 = acc[tm][tn][2] * alpha, v3 = acc[tm][tn][3] * alpha;
                acc[tm][tn][0] = v0; acc[tm][tn][1] = v1;
                acc[tm][tn][2] = v2; acc[tm][tn][3] = v3;
                *reinterpret_cast<float2*>(Cg + r_lo * N + col)       = make_float2(v0, v1);
                *reinterpret_cast<float2*>(Cg + (r_lo + 8) * N + col) = make_float2(v2, v3);
            }
        }
        if (!diag) {
            asm volatile("cp.async.wait_group 0;" ::: "memory");
            __syncthreads();
#pragma unroll
            for (int tm = 0; tm < 4; tm++) {
                const int m = wm0 + (tm << 4) + q;
#pragma unroll
                for (int tn = 0; tn < 8; tn++) {
                    const int n = wn0 + (tn << 3) + (s << 1);
                    sts_f(sb + (uint32_t)(n       * TPITCH + m)     * 4, acc[tm][tn][0]);
                    sts_f(sb + (uint32_t)((n + 1) * TPITCH + m)     * 4, acc[tm][tn][1]);
                    sts_f(sb + (uint32_t)(n       * TPITCH + m + 8) * 4, acc[tm][tn][2]);
                    sts_f(sb + (uint32_t)((n + 1) * TPITCH + m + 8) * 4, acc[tm][tn][3]);
                }
            }
            __syncthreads();
            float* dstrow = Cg + (size_t)(col0 + tid) * N + row0;
            const uint32_t srow = sb + (uint32_t)(tid * TPITCH) * 4;
#pragma unroll
            for (int j = 0; j < 128; j += 4) {
                float4 v = lds_f4(srow + j * 4);
                *reinterpret_cast<float4*>(dstrow + j) = v;
            }
        }
    }
}

// ---------------------------------------------------------------------------
// prepass: fp32 -> fp16 (RNE), embd and W in ONE launch
__global__ __launch_bounds__(256)
void round_h2(const float4* __restrict__ inE, __half2* __restrict__ outE, int n4e,
              const float4* __restrict__ inW, __half2* __restrict__ outW, int n4w)
{
    int i = blockIdx.x * 256 + threadIdx.x;
    if (i < n4e) {
        float4 v = inE[i];
        outE[2 * i]     = __floats2half2_rn(v.x, v.y);
        outE[2 * i + 1] = __floats2half2_rn(v.z, v.w);
    } else {
        int j = i - n4e;
        if (j < n4w) {
            float4 v = inW[j];
            outW[2 * j]     = __floats2half2_rn(v.x, v.y);
            outW[2 * j + 1] = __floats2half2_rn(v.z, v.w);
        }
    }
}

// row softmax over 2048 cols; writes probs*1024 as fp16 (normal range)
__global__ __launch_bounds__(256)
void softmax_kernel(const float* __restrict__ S, __half* __restrict__ P)
{
    const float4* p4 = reinterpret_cast<const float4*>(S + (size_t)blockIdx.x * SEQ);
    __half2* q2 = reinterpret_cast<__half2*>(P + (size_t)blockIdx.x * SEQ);
    const int tid  = threadIdx.x;
    const int lane = tid & 31;
    const int wid  = tid >> 5;
    __shared__ float red[8];

    float4 u0 = p4[tid], u1 = p4[tid + 256];
    float m = fmaxf(fmaxf(fmaxf(u0.x, u0.y), fmaxf(u0.z, u0.w)),
                    fmaxf(fmaxf(u1.x, u1.y), fmaxf(u1.z, u1.w)));
#pragma unroll
    for (int o = 16; o > 0; o >>= 1)
        m = fmaxf(m, __shfl_xor_sync(0xffffffffu, m, o));
    if (lane == 0) red[wid] = m;
    __syncthreads();
    float bm = red[0];
#pragma unroll
    for (int i = 1; i < 8; i++) bm = fmaxf(bm, red[i]);
    __syncthreads();

    u0.x = __expf(u0.x - bm); u0.y = __expf(u0.y - bm);
    u0.z = __expf(u0.z - bm); u0.w = __expf(u0.w - bm);
    u1.x = __expf(u1.x - bm); u1.y = __expf(u1.y - bm);
    u1.z = __expf(u1.z - bm); u1.w = __expf(u1.w - bm);
    float sum = (u0.x + u0.y) + (u0.z + u0.w) + (u1.x + u1.y) + (u1.z + u1.w);
#pragma unroll
    for (int o = 16; o > 0; o >>= 1)
        sum += __shfl_xor_sync(0xffffffffu, sum, o);
    if (lane == 0) red[wid] = sum;
    __syncthreads();
    float total = 0.f;
#pragma unroll
    for (int i = 0; i < 8; i++) total += red[i];
    const float k = 1024.f / total;       // scale by 1024 into fp16 normal range

    q2[2 * tid]           = __floats2half2_rn(u0.x * k, u0.y * k);
    q2[2 * tid + 1]       = __floats2half2_rn(u0.z * k, u0.w * k);
    q2[512 + 2 * tid]     = __floats2half2_rn(u1.x * k, u1.y * k);
    q2[512 + 2 * tid + 1] = __floats2half2_rn(u1.z * k, u1.w * k);
}

// ---------------------------------------------------------------------------
extern "C" void kernel_launch(void* const* d_in, const int* in_sizes, int n_in,
                              void* d_out, int out_size)
{
    const float* embd = (const float*)d_in[0];   // [8,2048,1024]
    const float* W    = (const float*)d_in[1];   // [1024,1024]
    const float* bias = (const float*)d_in[2];   // [1024]
    float* out = (float*)d_out;                  // [8,2048,1024]

    __half *et, *wt, *c, *ct, *p;
    float *s;
    cudaGetSymbolAddress((void**)&et, g_et);
    cudaGetSymbolAddress((void**)&wt, g_wt);
    cudaGetSymbolAddress((void**)&c,  g_c);
    cudaGetSymbolAddress((void**)&ct, g_ct);
    cudaGetSymbolAddress((void**)&s,  g_s);
    cudaGetSymbolAddress((void**)&p,  g_p);

    cudaFuncSetAttribute(tc_gemm<0>, cudaFuncAttributeMaxDynamicSharedMemorySize, DSMEM);
    cudaFuncSetAttribute(tc_gemm<1>, cudaFuncAttributeMaxDynamicSharedMemorySize, DSMEM);
    cudaFuncSetAttribute(tc_gemm<3>, cudaFuncAttributeMaxDynamicSharedMemorySize, DSMEM);

    // one-time host resources (no device memory involved)
    static cudaStream_t sA = nullptr;
    static cudaEvent_t evG2[BATCH], evSm[BATCH];
    if (sA == nullptr) {
        cudaStreamCreateWithFlags(&sA, cudaStreamNonBlocking);
        for (int b = 0; b < BATCH; b++) {
            cudaEventCreateWithFlags(&evG2[b], cudaEventDisableTiming);
            cudaEventCreateWithFlags(&evSm[b], cudaEventDisableTiming);
        }
    }

    const float scale = 0.03125f;  // 1/sqrt(1024)
    const size_t sC = (size_t)SEQ * OUTD;   // per-batch c elems
    const size_t sS = (size_t)SEQ * SEQ;    // per-batch score elems

    // prepass: round inputs to fp16 (single launch, default stream)
    {
        int n4e = BATCH * SEQ * EMBD / 4;
        int n4w = OUTD * EMBD / 4;
        int total = n4e + n4w;
        round_h2<<<(total + 255) / 256, 256>>>((const float4*)embd, (__half2*)et, n4e,
                                               (const float4*)W, (__half2*)wt, n4w);
    }

    // 1) c = embd @ W^T + b  (NT), writes c (fp16) AND c^T (fp16)
    {
        dim3 grid(OUTD / 128, (BATCH * SEQ) / 128, 1);
        tc_gemm<0><<<grid, 128, DSMEM>>>(et, wt, bias, nullptr, c, ct,
                                         OUTD, EMBD, 1.0f, 0, 0, 0);
    }

    // 2) GEMM2 per batch on default stream; softmax(b) forked onto sA as soon
    //    as GEMM2(b) completes, overlapping with GEMM2(b+1..)/GEMM3(0..).
    {
        dim3 grid(136, 1, 1);
        for (int b = 0; b < BATCH; b++) {
            tc_gemm<3><<<grid, 128, DSMEM>>>(c + (size_t)b * sC, c + (size_t)b * sC,
                                             nullptr, s + (size_t)b * sS,
                                             nullptr, nullptr,
                                             SEQ, OUTD, scale, 0, 0, 0);
            cudaEventRecord(evG2[b], 0);
            cudaStreamWaitEvent(sA, evG2[b], 0);
            softmax_kernel<<<SEQ, 256, 0, sA>>>(s + (size_t)b * sS,
                                                p + (size_t)b * sS);
            cudaEventRecord(evSm[b], sA);
        }
    }

    // 3) GEMM3 per batch on default stream, gated on that batch's softmax.
    //    (joins the fork: the last wait consumes sA's final captured event)
    {
        dim3 grid(OUTD / 128, SEQ / 128, 1);
        for (int b = 0; b < BATCH; b++) {
            cudaStreamWaitEvent(0, evSm[b], 0);
            tc_gemm<1><<<grid, 128, DSMEM>>>(p + (size_t)b * sS,
                                             ct + (size_t)b * sC,
                                             nullptr,
                                             out + (size_t)b * sC,
                                             nullptr, nullptr,
                                             OUTD, SEQ, 1.0f / 1024.f, 0, 0, 0);
        }
    }
}

// round 14
// speedup vs baseline: 1.3835x; 1.3835x over previous
#include <cuda_runtime.h>
#include <cuda_fp16.h>
#include <cstdint>

#define BATCH 8
#define SEQ   2048
#define EMBD  1024
#define OUTD  1024

// Scratch (device globals; allocations are forbidden)
__device__ __align__(256) __half g_et[(size_t)BATCH * SEQ * EMBD];  // fp16 embd 32MB
__device__ __align__(256) __half g_wt[(size_t)OUTD * EMBD];         // fp16 W     2MB
__device__ __align__(256) __half g_c [(size_t)BATCH * SEQ * OUTD];  // c fp16    32MB
__device__ __align__(256) __half g_ct[(size_t)BATCH * OUTD * SEQ];  // c^T fp16  32MB
__device__ __align__(256) float  g_s [(size_t)BATCH * SEQ * SEQ];   // scores   128MB
__device__ __align__(256) __half g_p [(size_t)BATCH * SEQ * SEQ];   // probs*1024 64MB

// ---------------------------------------------------------------------------
__device__ __forceinline__ uint32_t smem_u32(const void* p) {
    uint32_t a;
    asm("{ .reg .u64 t; cvta.to.shared.u64 t, %1; cvt.u32.u64 %0, t; }"
        : "=r"(a) : "l"(p));
    return a;
}
__device__ __forceinline__ void sts_f(uint32_t a, float v) {
    asm volatile("st.shared.b32 [%0], %1;" :: "r"(a), "f"(v) : "memory");
}
__device__ __forceinline__ float4 lds_f4(uint32_t a) {
    float4 v;
    asm volatile("ld.shared.v4.f32 {%0,%1,%2,%3}, [%4];"
                 : "=f"(v.x), "=f"(v.y), "=f"(v.z), "=f"(v.w) : "r"(a));
    return v;
}
__device__ __forceinline__ void ldsm4(uint32_t addr, uint32_t& r0, uint32_t& r1,
                                      uint32_t& r2, uint32_t& r3) {
    asm volatile("ldmatrix.sync.aligned.m8n8.x4.shared.b16 {%0,%1,%2,%3}, [%4];"
                 : "=r"(r0), "=r"(r1), "=r"(r2), "=r"(r3) : "r"(addr));
}
// fp16 MMA, fp32 accumulate: m16n8k16
__device__ __forceinline__ void mma_f16(float c[4], uint32_t a0, uint32_t a1,
                                        uint32_t a2, uint32_t a3,
                                        uint32_t b0, uint32_t b1) {
    asm volatile(
        "mma.sync.aligned.m16n8k16.row.col.f32.f16.f16.f32 "
        "{%0,%1,%2,%3}, {%4,%5,%6,%7}, {%8,%9}, {%0,%1,%2,%3};"
        : "+f"(c[0]), "+f"(c[1]), "+f"(c[2]), "+f"(c[3])
        : "r"(a0), "r"(a1), "r"(a2), "r"(a3), "r"(b0), "r"(b1));
}
__device__ __forceinline__ uint32_t sw128(uint32_t bo) {
    return bo ^ ((bo >> 3) & 0x70);
}

// ---------------------------------------------------------------------------
// fp16 mma.sync GEMM (all NT): 128x128 CTA tile, BK=64, 4 warps, warp 64x64.
// 128 threads, 2 CTAs/SM.  (R9/R12 champion configuration)
// MODE 0: +bias, write C fp16 AND C^T fp16                (GEMM1)
// MODE 1: *alpha, write C fp32                             (GEMM3)
// MODE 3: *alpha, fp32, SYMMETRIC triangular + mirror      (GEMM2)
// ---------------------------------------------------------------------------
#define STG     3
#define A_TB    16384                    // 128 rows x 128B
#define SB_OFF  (STG * A_TB)             // 49152
#define B_TB    16384
#define DSMEM   (SB_OFF + STG * B_TB + 1024)
#define TPITCH  132                      // transpose staging pitch (floats)

template <int MODE>
__global__ __launch_bounds__(128, 2)
void tc_gemm(const __half* __restrict__ Ag, const __half* __restrict__ Bg,
             const float* __restrict__ bias,
             float* __restrict__ Cg,            // fp32 out (MODE 1,3)
             __half* __restrict__ Ch,           // fp16 out (MODE 0)
             __half* __restrict__ CTg,          // fp16 transposed out (MODE 0)
             int N, int K, float alpha,
             size_t strA, size_t strB, size_t strC)
{
    extern __shared__ char dsm[];
    const uint32_t sb = (smem_u32(dsm) + 1023u) & ~1023u;

    Ag += (size_t)blockIdx.z * strA;
    Bg += (size_t)blockIdx.z * strB;
    if (MODE != 0) Cg += (size_t)blockIdx.z * strC;

    const int tid  = threadIdx.x;
    const int lane = tid & 31;
    const int wid  = tid >> 5;           // 0..3
    const int wm0  = (wid & 1) * 64;     // warp m offset
    const int wn0  = (wid >> 1) * 64;    // warp n offset

    int row0, col0;
    if (MODE == 3) {
        const int t = blockIdx.x;
        int r = (int)((sqrtf(8.0f * (float)t + 1.0f) - 1.0f) * 0.5f);
        while ((r + 1) * (r + 2) / 2 <= t) r++;
        while (r * (r + 1) / 2 > t)        r--;
        const int cc = t - r * (r + 1) / 2;
        row0 = r  * 128;
        col0 = cc * 128;
    } else {
        row0 = blockIdx.y * 128;
        col0 = blockIdx.x * 128;
    }

    const int NCH = K >> 6;              // BK = 64 fp16
    const int q = lane >> 2;             // 0..7 (fragment row)
    const int s = lane & 3;              // 0..3

    // ldmatrix per-lane constants
    const uint32_t tb   = ((lane >> 3) & 1) << 3;   // +8 rows for odd tiles
    const uint32_t th16 = ((lane >> 4) & 1) << 4;   // +16B => k 8..15
    const uint32_t xr   = (uint32_t)(lane & 7) << 4;
    uint32_t roffA[4], roffB[4];
#pragma unroll
    for (int t4 = 0; t4 < 4; t4++) {
        roffA[t4] = (uint32_t)(wm0 + (t4 << 4) + tb + (lane & 7)) << 7;
        roffB[t4] = (uint32_t)(wn0 + (t4 << 4) + tb + (lane & 7)) << 7;
    }

    float acc[4][8][4];
#pragma unroll
    for (int i = 0; i < 4; i++)
#pragma unroll
        for (int j = 0; j < 8; j++)
#pragma unroll
            for (int r = 0; r < 4; r++) acc[i][j][r] = 0.f;

    auto issue = [&](int ch, int st) {
        const int k0 = ch << 6;                    // fp16 elements
#pragma unroll
        for (int i = 0; i < 16; i++) {
            int g   = tid + (i << 7);              // 0..2047
            int isB = g >> 10;
            int gl  = g & 1023;
            int r   = gl >> 3;                     // row 0..127
            int gg  = gl & 7;                      // 16B granule (8 fp16)
            const __half* src = (isB ? Bg + (size_t)(col0 + r) * K
                                     : Ag + (size_t)(row0 + r) * K) + k0 + (gg << 3);
            uint32_t dst = sb + (isB ? SB_OFF : 0) + st * B_TB
                         + sw128((r << 7) + (gg << 4));
            asm volatile("cp.async.cg.shared.global [%0], [%1], 16;"
                         :: "r"(dst), "l"(src) : "memory");
        }
        asm volatile("cp.async.commit_group;" ::: "memory");
    };

    auto step = [&](int ch, const int st) {
        asm volatile("cp.async.wait_group 1;" ::: "memory");
        __syncthreads();
        if (ch + 2 < NCH) issue(ch + 2, (st + 2) % STG);
        else asm volatile("cp.async.commit_group;" ::: "memory");

        const uint32_t ab = sb + st * A_TB;
        const uint32_t bb = sb + SB_OFF + st * B_TB;

#pragma unroll
        for (int ks = 0; ks < 4; ks++) {           // 4 x k16 = BK 64
            const uint32_t kx = (((uint32_t)ks << 5) + th16) ^ xr;
            uint32_t af[16], bf[16];
#pragma unroll
            for (int tp = 0; tp < 4; tp++) {
                ldsm4(bb + roffB[tp] + kx,
                      bf[(tp * 2) * 2], bf[(tp * 2 + 1) * 2],
                      bf[(tp * 2) * 2 + 1], bf[(tp * 2 + 1) * 2 + 1]);
            }
#pragma unroll
            for (int tm = 0; tm < 4; tm++)
                ldsm4(ab + roffA[tm] + kx,
                      af[tm * 4], af[tm * 4 + 1], af[tm * 4 + 2], af[tm * 4 + 3]);
#pragma unroll
            for (int tm = 0; tm < 4; tm++)
#pragma unroll
                for (int tn = 0; tn < 8; tn++)
                    mma_f16(acc[tm][tn], af[tm * 4], af[tm * 4 + 1],
                            af[tm * 4 + 2], af[tm * 4 + 3],
                            bf[tn * 2], bf[tn * 2 + 1]);
        }
    };

    issue(0, 0);
    issue(1, 1);

    int ch = 0;
#pragma unroll 1
    for (; ch + 3 <= NCH; ch += 3) {
        step(ch,     0);
        step(ch + 1, 1);
        step(ch + 2, 2);
    }
    if (ch < NCH) { step(ch, 0); ch++; }
    if (ch < NCH) { step(ch, 1); }

    // -------- epilogue --------
    if (MODE == 0) {
        // bias add, round to fp16, write C (fp16) and stage for C^T
#pragma unroll
        for (int tm = 0; tm < 4; tm++) {
            const size_t r_lo = (size_t)row0 + wm0 + (tm << 4) + q;
#pragma unroll
            for (int tn = 0; tn < 8; tn++) {
                const int col = col0 + wn0 + (tn << 3) + (s << 1);
                const float b0 = __ldg(bias + col), b1 = __ldg(bias + col + 1);
                __half h0 = __float2half_rn(acc[tm][tn][0] + b0);
                __half h1 = __float2half_rn(acc[tm][tn][1] + b1);
                __half h2 = __float2half_rn(acc[tm][tn][2] + b0);
                __half h3 = __float2half_rn(acc[tm][tn][3] + b1);
                acc[tm][tn][0] = __half2float(h0);
                acc[tm][tn][1] = __half2float(h1);
                acc[tm][tn][2] = __half2float(h2);
                acc[tm][tn][3] = __half2float(h3);
                *reinterpret_cast<__half2*>(Ch + r_lo * N + col) =
                    __halves2half2(h0, h1);
                *reinterpret_cast<__half2*>(Ch + (r_lo + 8) * N + col) =
                    __halves2half2(h2, h3);
            }
        }
        // transpose-stage fp32 in smem, write C^T fp16 coalesced
        asm volatile("cp.async.wait_group 0;" ::: "memory");
        __syncthreads();
#pragma unroll
        for (int tm = 0; tm < 4; tm++) {
            const int m = wm0 + (tm << 4) + q;
#pragma unroll
            for (int tn = 0; tn < 8; tn++) {
                const int n = wn0 + (tn << 3) + (s << 1);
                sts_f(sb + (uint32_t)(n       * TPITCH + m)     * 4, acc[tm][tn][0]);
                sts_f(sb + (uint32_t)((n + 1) * TPITCH + m)     * 4, acc[tm][tn][1]);
                sts_f(sb + (uint32_t)(n       * TPITCH + m + 8) * 4, acc[tm][tn][2]);
                sts_f(sb + (uint32_t)((n + 1) * TPITCH + m + 8) * 4, acc[tm][tn][3]);
            }
        }
        __syncthreads();
        const int b  = row0 >> 11;           // batch (rows are batch-major)
        const int m2 = row0 & 2047;
        __half* dstrow = CTg + (size_t)b * OUTD * SEQ + (size_t)(col0 + tid) * SEQ + m2;
        const uint32_t srow = sb + (uint32_t)(tid * TPITCH) * 4;
#pragma unroll
        for (int j = 0; j < 128; j += 4) {
            float4 v = lds_f4(srow + j * 4);
            *reinterpret_cast<__half2*>(dstrow + j)     = __floats2half2_rn(v.x, v.y);
            *reinterpret_cast<__half2*>(dstrow + j + 2) = __floats2half2_rn(v.z, v.w);
        }
    } else if (MODE == 1) {
#pragma unroll
        for (int tm = 0; tm < 4; tm++) {
            const size_t r_lo = (size_t)row0 + wm0 + (tm << 4) + q;
#pragma unroll
            for (int tn = 0; tn < 8; tn++) {
                const int col = col0 + wn0 + (tn << 3) + (s << 1);
                *reinterpret_cast<float2*>(Cg + r_lo * N + col) =
                    make_float2(acc[tm][tn][0] * alpha, acc[tm][tn][1] * alpha);
                *reinterpret_cast<float2*>(Cg + (r_lo + 8) * N + col) =
                    make_float2(acc[tm][tn][2] * alpha, acc[tm][tn][3] * alpha);
            }
        }
    } else {  // MODE 3
        const bool diag = (row0 == col0);
#pragma unroll
        for (int tm = 0; tm < 4; tm++) {
            const size_t r_lo = (size_t)row0 + wm0 + (tm << 4) + q;
#pragma unroll
            for (int tn = 0; tn < 8; tn++) {
                const int col = col0 + wn0 + (tn << 3) + (s << 1);
                float v0 = acc[tm][tn][0] * alpha, v1 = acc[tm][tn][1] * alpha;
                float v2 = acc[tm][tn][2] * alpha, v3 = acc[tm][tn][3] * alpha;
                acc[tm][tn][0] = v0; acc[tm][tn][1] = v1;
                acc[tm][tn][2] = v2; acc[tm][tn][3] = v3;
                *reinterpret_cast<float2*>(Cg + r_lo * N + col)       = make_float2(v0, v1);
                *reinterpret_cast<float2*>(Cg + (r_lo + 8) * N + col) = make_float2(v2, v3);
            }
        }
        if (!diag) {
            asm volatile("cp.async.wait_group 0;" ::: "memory");
            __syncthreads();
#pragma unroll
            for (int tm = 0; tm < 4; tm++) {
                const int m = wm0 + (tm << 4) + q;
#pragma unroll
                for (int tn = 0; tn < 8; tn++) {
                    const int n = wn0 + (tn << 3) + (s << 1);
                    sts_f(sb + (uint32_t)(n       * TPITCH + m)     * 4, acc[tm][tn][0]);
                    sts_f(sb + (uint32_t)((n + 1) * TPITCH + m)     * 4, acc[tm][tn][1]);
                    sts_f(sb + (uint32_t)(n       * TPITCH + m + 8) * 4, acc[tm][tn][2]);
                    sts_f(sb + (uint32_t)((n + 1) * TPITCH + m + 8) * 4, acc[tm][tn][3]);
                }
            }
            __syncthreads();
            float* dstrow = Cg + (size_t)(col0 + tid) * N + row0;
            const uint32_t srow = sb + (uint32_t)(tid * TPITCH) * 4;
#pragma unroll
            for (int j = 0; j < 128; j += 4) {
                float4 v = lds_f4(srow + j * 4);
                *reinterpret_cast<float4*>(dstrow + j) = v;
            }
        }
    }
}

// ---------------------------------------------------------------------------
// prepass: fp32 -> fp16 (RNE), embd and W in ONE launch
__global__ __launch_bounds__(256)
void round_h2(const float4* __restrict__ inE, __half2* __restrict__ outE, int n4e,
              const float4* __restrict__ inW, __half2* __restrict__ outW, int n4w)
{
    int i = blockIdx.x * 256 + threadIdx.x;
    if (i < n4e) {
        float4 v = inE[i];
        outE[2 * i]     = __floats2half2_rn(v.x, v.y);
        outE[2 * i + 1] = __floats2half2_rn(v.z, v.w);
    } else {
        int j = i - n4e;
        if (j < n4w) {
            float4 v = inW[j];
            outW[2 * j]     = __floats2half2_rn(v.x, v.y);
            outW[2 * j + 1] = __floats2half2_rn(v.z, v.w);
        }
    }
}

// row softmax over 2048 cols; writes probs*1024 as fp16 (normal range)
__global__ __launch_bounds__(256)
void softmax_kernel(const float* __restrict__ S, __half* __restrict__ P)
{
    const float4* p4 = reinterpret_cast<const float4*>(S + (size_t)blockIdx.x * SEQ);
    __half2* q2 = reinterpret_cast<__half2*>(P + (size_t)blockIdx.x * SEQ);
    const int tid  = threadIdx.x;
    const int lane = tid & 31;
    const int wid  = tid >> 5;
    __shared__ float red[8];

    float4 u0 = p4[tid], u1 = p4[tid + 256];
    float m = fmaxf(fmaxf(fmaxf(u0.x, u0.y), fmaxf(u0.z, u0.w)),
                    fmaxf(fmaxf(u1.x, u1.y), fmaxf(u1.z, u1.w)));
#pragma unroll
    for (int o = 16; o > 0; o >>= 1)
        m = fmaxf(m, __shfl_xor_sync(0xffffffffu, m, o));
    if (lane == 0) red[wid] = m;
    __syncthreads();
    float bm = red[0];
#pragma unroll
    for (int i = 1; i < 8; i++) bm = fmaxf(bm, red[i]);
    __syncthreads();

    u0.x = __expf(u0.x - bm); u0.y = __expf(u0.y - bm);
    u0.z = __expf(u0.z - bm); u0.w = __expf(u0.w - bm);
    u1.x = __expf(u1.x - bm); u1.y = __expf(u1.y - bm);
    u1.z = __expf(u1.z - bm); u1.w = __expf(u1.w - bm);
    float sum = (u0.x + u0.y) + (u0.z + u0.w) + (u1.x + u1.y) + (u1.z + u1.w);
#pragma unroll
    for (int o = 16; o > 0; o >>= 1)
        sum += __shfl_xor_sync(0xffffffffu, sum, o);
    if (lane == 0) red[wid] = sum;
    __syncthreads();
    float total = 0.f;
#pragma unroll
    for (int i = 0; i < 8; i++) total += red[i];
    const float k = 1024.f / total;       // scale by 1024 into fp16 normal range

    q2[2 * tid]           = __floats2half2_rn(u0.x * k, u0.y * k);
    q2[2 * tid + 1]       = __floats2half2_rn(u0.z * k, u0.w * k);
    q2[512 + 2 * tid]     = __floats2half2_rn(u1.x * k, u1.y * k);
    q2[512 + 2 * tid + 1] = __floats2half2_rn(u1.z * k, u1.w * k);
}

// ---------------------------------------------------------------------------
extern "C" void kernel_launch(void* const* d_in, const int* in_sizes, int n_in,
                              void* d_out, int out_size)
{
    const float* embd = (const float*)d_in[0];   // [8,2048,1024]
    const float* W    = (const float*)d_in[1];   // [1024,1024]
    const float* bias = (const float*)d_in[2];   // [1024]
    float* out = (float*)d_out;                  // [8,2048,1024]

    __half *et, *wt, *c, *ct, *p;
    float *s;
    cudaGetSymbolAddress((void**)&et, g_et);
    cudaGetSymbolAddress((void**)&wt, g_wt);
    cudaGetSymbolAddress((void**)&c,  g_c);
    cudaGetSymbolAddress((void**)&ct, g_ct);
    cudaGetSymbolAddress((void**)&s,  g_s);
    cudaGetSymbolAddress((void**)&p,  g_p);

    cudaFuncSetAttribute(tc_gemm<0>, cudaFuncAttributeMaxDynamicSharedMemorySize, DSMEM);
    cudaFuncSetAttribute(tc_gemm<1>, cudaFuncAttributeMaxDynamicSharedMemorySize, DSMEM);
    cudaFuncSetAttribute(tc_gemm<3>, cudaFuncAttributeMaxDynamicSharedMemorySize, DSMEM);

    // one-time host resources (no device memory involved)
    static cudaStream_t sA = nullptr;
    static cudaEvent_t evG2[2], evSm[2];
    if (sA == nullptr) {
        cudaStreamCreateWithFlags(&sA, cudaStreamNonBlocking);
        for (int h = 0; h < 2; h++) {
            cudaEventCreateWithFlags(&evG2[h], cudaEventDisableTiming);
            cudaEventCreateWithFlags(&evSm[h], cudaEventDisableTiming);
        }
    }

    const float scale = 0.03125f;  // 1/sqrt(1024)
    const size_t sC = (size_t)SEQ * OUTD;   // per-batch c elems
    const size_t sS = (size_t)SEQ * SEQ;    // per-batch score elems
    const int HB = BATCH / 2;               // 4 batches per half

    // prepass: round inputs to fp16 (single launch, default stream)
    {
        int n4e = BATCH * SEQ * EMBD / 4;
        int n4w = OUTD * EMBD / 4;
        int total = n4e + n4w;
        round_h2<<<(total + 255) / 256, 256>>>((const float4*)embd, (__half2*)et, n4e,
                                               (const float4*)W, (__half2*)wt, n4w);
    }

    // 1) c = embd @ W^T + b  (NT), writes c (fp16) AND c^T (fp16)
    {
        dim3 grid(OUTD / 128, (BATCH * SEQ) / 128, 1);
        tc_gemm<0><<<grid, 128, DSMEM>>>(et, wt, bias, nullptr, c, ct,
                                         OUTD, EMBD, 1.0f, 0, 0, 0);
    }

    // 2) GEMM2 in two half-batch launches (544 CTAs each — full waves).
    //    softmax for half h forked onto sA as soon as GEMM2 half h completes,
    //    overlapping GEMM2 half 2 / GEMM3 half 1.
    {
        dim3 grid(136, 1, HB);
        for (int h = 0; h < 2; h++) {
            const size_t boff = (size_t)h * HB;
            tc_gemm<3><<<grid, 128, DSMEM>>>(c + boff * sC, c + boff * sC,
                                             nullptr, s + boff * sS,
                                             nullptr, nullptr,
                                             SEQ, OUTD, scale, sC, sC, sS);
            cudaEventRecord(evG2[h], 0);
            cudaStreamWaitEvent(sA, evG2[h], 0);
            softmax_kernel<<<HB * SEQ, 256, 0, sA>>>(s + boff * sS,
                                                     p + boff * sS);
            cudaEventRecord(evSm[h], sA);
        }
    }

    // 3) GEMM3 in two half-batch launches (512 CTAs each), each gated on its
    //    half's softmax. Second wait joins the forked stream back.
    {
        dim3 grid(OUTD / 128, SEQ / 128, HB);
        for (int h = 0; h < 2; h++) {
            const size_t boff = (size_t)h * HB;
            cudaStreamWaitEvent(0, evSm[h], 0);
            tc_gemm<1><<<grid, 128, DSMEM>>>(p + boff * sS,
                                             ct + boff * sC,
                                             nullptr,
                                             out + boff * sC,
                                             nullptr, nullptr,
                                             OUTD, SEQ, 1.0f / 1024.f,
                                             sS, sC, sC);
        }
    }
}

// round 15
// speedup vs baseline: 1.4495x; 1.0477x over previous
#include <cuda_runtime.h>
#include <cuda_fp16.h>
#include <cstdint>

#define BATCH 8
#define SEQ   2048
#define EMBD  1024
#define OUTD  1024

// Scratch (device globals; allocations are forbidden)
__device__ __align__(256) __half g_et[(size_t)BATCH * SEQ * EMBD];  // fp16 embd 32MB
__device__ __align__(256) __half g_wt[(size_t)OUTD * EMBD];         // fp16 W     2MB
__device__ __align__(256) __half g_c [(size_t)BATCH * SEQ * OUTD];  // c fp16    32MB
__device__ __align__(256) __half g_ct[(size_t)BATCH * OUTD * SEQ];  // c^T fp16  32MB
__device__ __align__(256) __half g_s [(size_t)BATCH * SEQ * SEQ];   // logits fp16 64MB
__device__ __align__(256) __half g_p [(size_t)BATCH * SEQ * SEQ];   // probs*1024 64MB

// ---------------------------------------------------------------------------
__device__ __forceinline__ uint32_t smem_u32(const void* p) {
    uint32_t a;
    asm("{ .reg .u64 t; cvta.to.shared.u64 t, %1; cvt.u32.u64 %0, t; }"
        : "=r"(a) : "l"(p));
    return a;
}
__device__ __forceinline__ void sts_f(uint32_t a, float v) {
    asm volatile("st.shared.b32 [%0], %1;" :: "r"(a), "f"(v) : "memory");
}
__device__ __forceinline__ float4 lds_f4(uint32_t a) {
    float4 v;
    asm volatile("ld.shared.v4.f32 {%0,%1,%2,%3}, [%4];"
                 : "=f"(v.x), "=f"(v.y), "=f"(v.z), "=f"(v.w) : "r"(a));
    return v;
}
__device__ __forceinline__ void ldsm4(uint32_t addr, uint32_t& r0, uint32_t& r1,
                                      uint32_t& r2, uint32_t& r3) {
    asm volatile("ldmatrix.sync.aligned.m8n8.x4.shared.b16 {%0,%1,%2,%3}, [%4];"
                 : "=r"(r0), "=r"(r1), "=r"(r2), "=r"(r3) : "r"(addr));
}
// fp16 MMA, fp32 accumulate: m16n8k16
__device__ __forceinline__ void mma_f16(float c[4], uint32_t a0, uint32_t a1,
                                        uint32_t a2, uint32_t a3,
                                        uint32_t b0, uint32_t b1) {
    asm volatile(
        "mma.sync.aligned.m16n8k16.row.col.f32.f16.f16.f32 "
        "{%0,%1,%2,%3}, {%4,%5,%6,%7}, {%8,%9}, {%0,%1,%2,%3};"
        : "+f"(c[0]), "+f"(c[1]), "+f"(c[2]), "+f"(c[3])
        : "r"(a0), "r"(a1), "r"(a2), "r"(a3), "r"(b0), "r"(b1));
}
__device__ __forceinline__ uint32_t sw128(uint32_t bo) {
    return bo ^ ((bo >> 3) & 0x70);
}

// ---------------------------------------------------------------------------
// fp16 mma.sync GEMM (all NT): 128x128 CTA tile, BK=64, 4 warps, warp 64x64.
// 128 threads, 2 CTAs/SM.  (R9/R12 champion configuration)
// MODE 0: +bias, write C fp16 AND C^T fp16                (GEMM1)
// MODE 1: *alpha, write C fp32                             (GEMM3)
// MODE 3: *alpha, write fp16 logits, SYMMETRIC tri+mirror  (GEMM2)
// ---------------------------------------------------------------------------
#define STG     3
#define A_TB    16384                    // 128 rows x 128B
#define SB_OFF  (STG * A_TB)             // 49152
#define B_TB    16384
#define DSMEM   (SB_OFF + STG * B_TB + 1024)
#define TPITCH  132                      // transpose staging pitch (floats)

template <int MODE>
__global__ __launch_bounds__(128, 2)
void tc_gemm(const __half* __restrict__ Ag, const __half* __restrict__ Bg,
             const float* __restrict__ bias,
             float* __restrict__ Cg,            // fp32 out (MODE 1)
             __half* __restrict__ Ch,           // fp16 out (MODE 0, 3)
             __half* __restrict__ CTg,          // fp16 transposed out (MODE 0)
             int N, int K, float alpha,
             size_t strA, size_t strB, size_t strC)
{
    extern __shared__ char dsm[];
    const uint32_t sb = (smem_u32(dsm) + 1023u) & ~1023u;

    Ag += (size_t)blockIdx.z * strA;
    Bg += (size_t)blockIdx.z * strB;
    if (MODE == 1) Cg += (size_t)blockIdx.z * strC;
    if (MODE == 3) Ch += (size_t)blockIdx.z * strC;

    const int tid  = threadIdx.x;
    const int lane = tid & 31;
    const int wid  = tid >> 5;           // 0..3
    const int wm0  = (wid & 1) * 64;     // warp m offset
    const int wn0  = (wid >> 1) * 64;    // warp n offset

    int row0, col0;
    if (MODE == 3) {
        const int t = blockIdx.x;
        int r = (int)((sqrtf(8.0f * (float)t + 1.0f) - 1.0f) * 0.5f);
        while ((r + 1) * (r + 2) / 2 <= t) r++;
        while (r * (r + 1) / 2 > t)        r--;
        const int cc = t - r * (r + 1) / 2;
        row0 = r  * 128;
        col0 = cc * 128;
    } else {
        row0 = blockIdx.y * 128;
        col0 = blockIdx.x * 128;
    }

    const int NCH = K >> 6;              // BK = 64 fp16
    const int q = lane >> 2;             // 0..7 (fragment row)
    const int s = lane & 3;              // 0..3

    // ldmatrix per-lane constants
    const uint32_t tb   = ((lane >> 3) & 1) << 3;   // +8 rows for odd tiles
    const uint32_t th16 = ((lane >> 4) & 1) << 4;   // +16B => k 8..15
    const uint32_t xr   = (uint32_t)(lane & 7) << 4;
    uint32_t roffA[4], roffB[4];
#pragma unroll
    for (int t4 = 0; t4 < 4; t4++) {
        roffA[t4] = (uint32_t)(wm0 + (t4 << 4) + tb + (lane & 7)) << 7;
        roffB[t4] = (uint32_t)(wn0 + (t4 << 4) + tb + (lane & 7)) << 7;
    }

    float acc[4][8][4];
#pragma unroll
    for (int i = 0; i < 4; i++)
#pragma unroll
        for (int j = 0; j < 8; j++)
#pragma unroll
            for (int r = 0; r < 4; r++) acc[i][j][r] = 0.f;

    auto issue = [&](int ch, int st) {
        const int k0 = ch << 6;                    // fp16 elements
#pragma unroll
        for (int i = 0; i < 16; i++) {
            int g   = tid + (i << 7);              // 0..2047
            int isB = g >> 10;
            int gl  = g & 1023;
            int r   = gl >> 3;                     // row 0..127
            int gg  = gl & 7;                      // 16B granule (8 fp16)
            const __half* src = (isB ? Bg + (size_t)(col0 + r) * K
                                     : Ag + (size_t)(row0 + r) * K) + k0 + (gg << 3);
            uint32_t dst = sb + (isB ? SB_OFF : 0) + st * B_TB
                         + sw128((r << 7) + (gg << 4));
            asm volatile("cp.async.cg.shared.global [%0], [%1], 16;"
                         :: "r"(dst), "l"(src) : "memory");
        }
        asm volatile("cp.async.commit_group;" ::: "memory");
    };

    auto step = [&](int ch, const int st) {
        asm volatile("cp.async.wait_group 1;" ::: "memory");
        __syncthreads();
        if (ch + 2 < NCH) issue(ch + 2, (st + 2) % STG);
        else asm volatile("cp.async.commit_group;" ::: "memory");

        const uint32_t ab = sb + st * A_TB;
        const uint32_t bb = sb + SB_OFF + st * B_TB;

#pragma unroll
        for (int ks = 0; ks < 4; ks++) {           // 4 x k16 = BK 64
            const uint32_t kx = (((uint32_t)ks << 5) + th16) ^ xr;
            uint32_t af[16], bf[16];
#pragma unroll
            for (int tp = 0; tp < 4; tp++) {
                ldsm4(bb + roffB[tp] + kx,
                      bf[(tp * 2) * 2], bf[(tp * 2 + 1) * 2],
                      bf[(tp * 2) * 2 + 1], bf[(tp * 2 + 1) * 2 + 1]);
            }
#pragma unroll
            for (int tm = 0; tm < 4; tm++)
                ldsm4(ab + roffA[tm] + kx,
                      af[tm * 4], af[tm * 4 + 1], af[tm * 4 + 2], af[tm * 4 + 3]);
#pragma unroll
            for (int tm = 0; tm < 4; tm++)
#pragma unroll
                for (int tn = 0; tn < 8; tn++)
                    mma_f16(acc[tm][tn], af[tm * 4], af[tm * 4 + 1],
                            af[tm * 4 + 2], af[tm * 4 + 3],
                            bf[tn * 2], bf[tn * 2 + 1]);
        }
    };

    issue(0, 0);
    issue(1, 1);

    int ch = 0;
#pragma unroll 1
    for (; ch + 3 <= NCH; ch += 3) {
        step(ch,     0);
        step(ch + 1, 1);
        step(ch + 2, 2);
    }
    if (ch < NCH) { step(ch, 0); ch++; }
    if (ch < NCH) { step(ch, 1); }

    // -------- epilogue --------
    if (MODE == 0) {
        // bias add, round to fp16, write C (fp16) and stage for C^T
#pragma unroll
        for (int tm = 0; tm < 4; tm++) {
            const size_t r_lo = (size_t)row0 + wm0 + (tm << 4) + q;
#pragma unroll
            for (int tn = 0; tn < 8; tn++) {
                const int col = col0 + wn0 + (tn << 3) + (s << 1);
                const float b0 = __ldg(bias + col), b1 = __ldg(bias + col + 1);
                __half h0 = __float2half_rn(acc[tm][tn][0] + b0);
                __half h1 = __float2half_rn(acc[tm][tn][1] + b1);
                __half h2 = __float2half_rn(acc[tm][tn][2] + b0);
                __half h3 = __float2half_rn(acc[tm][tn][3] + b1);
                acc[tm][tn][0] = __half2float(h0);
                acc[tm][tn][1] = __half2float(h1);
                acc[tm][tn][2] = __half2float(h2);
                acc[tm][tn][3] = __half2float(h3);
                *reinterpret_cast<__half2*>(Ch + r_lo * N + col) =
                    __halves2half2(h0, h1);
                *reinterpret_cast<__half2*>(Ch + (r_lo + 8) * N + col) =
                    __halves2half2(h2, h3);
            }
        }
        // transpose-stage fp32 in smem, write C^T fp16 coalesced
        asm volatile("cp.async.wait_group 0;" ::: "memory");
        __syncthreads();
#pragma unroll
        for (int tm = 0; tm < 4; tm++) {
            const int m = wm0 + (tm << 4) + q;
#pragma unroll
            for (int tn = 0; tn < 8; tn++) {
                const int n = wn0 + (tn << 3) + (s << 1);
                sts_f(sb + (uint32_t)(n       * TPITCH + m)     * 4, acc[tm][tn][0]);
                sts_f(sb + (uint32_t)((n + 1) * TPITCH + m)     * 4, acc[tm][tn][1]);
                sts_f(sb + (uint32_t)(n       * TPITCH + m + 8) * 4, acc[tm][tn][2]);
                sts_f(sb + (uint32_t)((n + 1) * TPITCH + m + 8) * 4, acc[tm][tn][3]);
            }
        }
        __syncthreads();
        const int b  = row0 >> 11;           // batch (rows are batch-major)
        const int m2 = row0 & 2047;
        __half* dstrow = CTg + (size_t)b * OUTD * SEQ + (size_t)(col0 + tid) * SEQ + m2;
        const uint32_t srow = sb + (uint32_t)(tid * TPITCH) * 4;
#pragma unroll
        for (int j = 0; j < 128; j += 4) {
            float4 v = lds_f4(srow + j * 4);
            *reinterpret_cast<__half2*>(dstrow + j)     = __floats2half2_rn(v.x, v.y);
            *reinterpret_cast<__half2*>(dstrow + j + 2) = __floats2half2_rn(v.z, v.w);
        }
    } else if (MODE == 1) {
#pragma unroll
        for (int tm = 0; tm < 4; tm++) {
            const size_t r_lo = (size_t)row0 + wm0 + (tm << 4) + q;
#pragma unroll
            for (int tn = 0; tn < 8; tn++) {
                const int col = col0 + wn0 + (tn << 3) + (s << 1);
                *reinterpret_cast<float2*>(Cg + r_lo * N + col) =
                    make_float2(acc[tm][tn][0] * alpha, acc[tm][tn][1] * alpha);
                *reinterpret_cast<float2*>(Cg + (r_lo + 8) * N + col) =
                    make_float2(acc[tm][tn][2] * alpha, acc[tm][tn][3] * alpha);
            }
        }
    } else {  // MODE 3: fp16 logits, triangular + mirror
        const bool diag = (row0 == col0);
#pragma unroll
        for (int tm = 0; tm < 4; tm++) {
            const size_t r_lo = (size_t)row0 + wm0 + (tm << 4) + q;
#pragma unroll
            for (int tn = 0; tn < 8; tn++) {
                const int col = col0 + wn0 + (tn << 3) + (s << 1);
                float v0 = acc[tm][tn][0] * alpha, v1 = acc[tm][tn][1] * alpha;
                float v2 = acc[tm][tn][2] * alpha, v3 = acc[tm][tn][3] * alpha;
                acc[tm][tn][0] = v0; acc[tm][tn][1] = v1;
                acc[tm][tn][2] = v2; acc[tm][tn][3] = v3;
                *reinterpret_cast<__half2*>(Ch + r_lo * N + col) =
                    __floats2half2_rn(v0, v1);
                *reinterpret_cast<__half2*>(Ch + (r_lo + 8) * N + col) =
                    __floats2half2_rn(v2, v3);
            }
        }
        if (!diag) {
            asm volatile("cp.async.wait_group 0;" ::: "memory");
            __syncthreads();
#pragma unroll
            for (int tm = 0; tm < 4; tm++) {
                const int m = wm0 + (tm << 4) + q;
#pragma unroll
                for (int tn = 0; tn < 8; tn++) {
                    const int n = wn0 + (tn << 3) + (s << 1);
                    sts_f(sb + (uint32_t)(n       * TPITCH + m)     * 4, acc[tm][tn][0]);
                    sts_f(sb + (uint32_t)((n + 1) * TPITCH + m)     * 4, acc[tm][tn][1]);
                    sts_f(sb + (uint32_t)(n       * TPITCH + m + 8) * 4, acc[tm][tn][2]);
                    sts_f(sb + (uint32_t)((n + 1) * TPITCH + m + 8) * 4, acc[tm][tn][3]);
                }
            }
            __syncthreads();
            __half* dstrow = Ch + (size_t)(col0 + tid) * N + row0;
            const uint32_t srow = sb + (uint32_t)(tid * TPITCH) * 4;
#pragma unroll
            for (int j = 0; j < 128; j += 4) {
                float4 v = lds_f4(srow + j * 4);
                *reinterpret_cast<__half2*>(dstrow + j)     = __floats2half2_rn(v.x, v.y);
                *reinterpret_cast<__half2*>(dstrow + j + 2) = __floats2half2_rn(v.z, v.w);
            }
        }
    }
}

// ---------------------------------------------------------------------------
// prepass: fp32 -> fp16 (RNE), embd and W in ONE launch
__global__ __launch_bounds__(256)
void round_h2(const float4* __restrict__ inE, __half2* __restrict__ outE, int n4e,
              const float4* __restrict__ inW, __half2* __restrict__ outW, int n4w)
{
    int i = blockIdx.x * 256 + threadIdx.x;
    if (i < n4e) {
        float4 v = inE[i];
        outE[2 * i]     = __floats2half2_rn(v.x, v.y);
        outE[2 * i + 1] = __floats2half2_rn(v.z, v.w);
    } else {
        int j = i - n4e;
        if (j < n4w) {
            float4 v = inW[j];
            outW[2 * j]     = __floats2half2_rn(v.x, v.y);
            outW[2 * j + 1] = __floats2half2_rn(v.z, v.w);
        }
    }
}

// row softmax over 2048 fp16 logits; writes probs*1024 as fp16
__global__ __launch_bounds__(256)
void softmax_kernel(const __half* __restrict__ S, __half* __restrict__ P)
{
    const uint4* p4 = reinterpret_cast<const uint4*>(S + (size_t)blockIdx.x * SEQ);
    uint4* q4 = reinterpret_cast<uint4*>(P + (size_t)blockIdx.x * SEQ);
    const int tid  = threadIdx.x;
    const int lane = tid & 31;
    const int wid  = tid >> 5;
    __shared__ float red[8];

    // one uint4 = 8 fp16 per thread (2048 / 256)
    uint4 u = p4[tid];
    float v[8];
    {
        float2 f0 = __half22float2(*reinterpret_cast<__half2*>(&u.x));
        float2 f1 = __half22float2(*reinterpret_cast<__half2*>(&u.y));
        float2 f2 = __half22float2(*reinterpret_cast<__half2*>(&u.z));
        float2 f3 = __half22float2(*reinterpret_cast<__half2*>(&u.w));
        v[0] = f0.x; v[1] = f0.y; v[2] = f1.x; v[3] = f1.y;
        v[4] = f2.x; v[5] = f2.y; v[6] = f3.x; v[7] = f3.y;
    }
    float m = v[0];
#pragma unroll
    for (int k = 1; k < 8; k++) m = fmaxf(m, v[k]);
#pragma unroll
    for (int o = 16; o > 0; o >>= 1)
        m = fmaxf(m, __shfl_xor_sync(0xffffffffu, m, o));
    if (lane == 0) red[wid] = m;
    __syncthreads();
    float bm = red[0];
#pragma unroll
    for (int i = 1; i < 8; i++) bm = fmaxf(bm, red[i]);
    __syncthreads();

    float sum = 0.f;
#pragma unroll
    for (int k = 0; k < 8; k++) {
        v[k] = __expf(v[k] - bm);
        sum += v[k];
    }
#pragma unroll
    for (int o = 16; o > 0; o >>= 1)
        sum += __shfl_xor_sync(0xffffffffu, sum, o);
    if (lane == 0) red[wid] = sum;
    __syncthreads();
    float total = 0.f;
#pragma unroll
    for (int i = 0; i < 8; i++) total += red[i];
    const float k = 1024.f / total;       // scale by 1024 into fp16 normal range

    uint4 o4;
    *reinterpret_cast<__half2*>(&o4.x) = __floats2half2_rn(v[0] * k, v[1] * k);
    *reinterpret_cast<__half2*>(&o4.y) = __floats2half2_rn(v[2] * k, v[3] * k);
    *reinterpret_cast<__half2*>(&o4.z) = __floats2half2_rn(v[4] * k, v[5] * k);
    *reinterpret_cast<__half2*>(&o4.w) = __floats2half2_rn(v[6] * k, v[7] * k);
    q4[tid] = o4;
}

// ---------------------------------------------------------------------------
extern "C" void kernel_launch(void* const* d_in, const int* in_sizes, int n_in,
                              void* d_out, int out_size)
{
    const float* embd = (const float*)d_in[0];   // [8,2048,1024]
    const float* W    = (const float*)d_in[1];   // [1024,1024]
    const float* bias = (const float*)d_in[2];   // [1024]
    float* out = (float*)d_out;                  // [8,2048,1024]

    __half *et, *wt, *c, *ct, *p, *s;
    cudaGetSymbolAddress((void**)&et, g_et);
    cudaGetSymbolAddress((void**)&wt, g_wt);
    cudaGetSymbolAddress((void**)&c,  g_c);
    cudaGetSymbolAddress((void**)&ct, g_ct);
    cudaGetSymbolAddress((void**)&s,  g_s);
    cudaGetSymbolAddress((void**)&p,  g_p);

    cudaFuncSetAttribute(tc_gemm<0>, cudaFuncAttributeMaxDynamicSharedMemorySize, DSMEM);
    cudaFuncSetAttribute(tc_gemm<1>, cudaFuncAttributeMaxDynamicSharedMemorySize, DSMEM);
    cudaFuncSetAttribute(tc_gemm<3>, cudaFuncAttributeMaxDynamicSharedMemorySize, DSMEM);

    const float scale = 0.03125f;  // 1/sqrt(1024)

    // prepass: round inputs to fp16 (single launch)
    {
        int n4e = BATCH * SEQ * EMBD / 4;
        int n4w = OUTD * EMBD / 4;
        int total = n4e + n4w;
        round_h2<<<(total + 255) / 256, 256>>>((const float4*)embd, (__half2*)et, n4e,
                                               (const float4*)W, (__half2*)wt, n4w);
    }

    // 1) c = embd @ W^T + b  (NT), writes c (fp16) AND c^T (fp16)
    {
        dim3 grid(OUTD / 128, (BATCH * SEQ) / 128, 1);
        tc_gemm<0><<<grid, 128, DSMEM>>>(et, wt, bias, nullptr, c, ct,
                                         OUTD, EMBD, 1.0f, 0, 0, 0);
    }
    // 2) s = (c @ c^T) * scale per batch — symmetric: 136 triangular tiles,
    //    logits stored fp16
    {
        dim3 grid(136, 1, BATCH);
        tc_gemm<3><<<grid, 128, DSMEM>>>(c, c, nullptr, nullptr, s, nullptr,
                                         SEQ, OUTD, scale,
                                         (size_t)SEQ * OUTD, (size_t)SEQ * OUTD,
                                         (size_t)SEQ * SEQ);
    }
    // 3) softmax rows (fp16 in) -> probs*1024 fp16
    softmax_kernel<<<BATCH * SEQ, 256>>>(s, p);

    // 4) out = (P/1024) @ c  ==  P @ (c^T)^T * (1/1024)  (NT)
    {
        dim3 grid(OUTD / 128, SEQ / 128, BATCH);
        tc_gemm<1><<<grid, 128, DSMEM>>>(p, ct, nullptr, out, nullptr, nullptr,
                                         OUTD, SEQ, 1.0f / 1024.f,
                                         (size_t)SEQ * SEQ, (size_t)OUTD * SEQ,
                                         (size_t)SEQ * OUTD);
    }
}

// round 16
// speedup vs baseline: 1.5100x; 1.0417x over previous
#include <cuda_runtime.h>
#include <cuda_fp16.h>
#include <cstdint>

#define BATCH 8
#define SEQ   2048
#define EMBD  1024
#define OUTD  1024

// Scratch (device globals; allocations are forbidden)
__device__ __align__(256) __half g_et[(size_t)BATCH * SEQ * EMBD];  // fp16 embd 32MB
__device__ __align__(256) __half g_wt[(size_t)OUTD * EMBD];         // fp16 W     2MB
__device__ __align__(256) __half g_c [(size_t)BATCH * SEQ * OUTD];  // c fp16    32MB
__device__ __align__(256) float  g_s [(size_t)BATCH * SEQ * SEQ];   // logits   128MB
__device__ __align__(256) __half g_p [(size_t)BATCH * SEQ * SEQ];   // probs*1024 64MB

// ---------------------------------------------------------------------------
__device__ __forceinline__ uint32_t smem_u32(const void* p) {
    uint32_t a;
    asm("{ .reg .u64 t; cvta.to.shared.u64 t, %1; cvt.u32.u64 %0, t; }"
        : "=r"(a) : "l"(p));
    return a;
}
__device__ __forceinline__ void sts_f(uint32_t a, float v) {
    asm volatile("st.shared.b32 [%0], %1;" :: "r"(a), "f"(v) : "memory");
}
__device__ __forceinline__ float4 lds_f4(uint32_t a) {
    float4 v;
    asm volatile("ld.shared.v4.f32 {%0,%1,%2,%3}, [%4];"
                 : "=f"(v.x), "=f"(v.y), "=f"(v.z), "=f"(v.w) : "r"(a));
    return v;
}
__device__ __forceinline__ void ldsm4(uint32_t addr, uint32_t& r0, uint32_t& r1,
                                      uint32_t& r2, uint32_t& r3) {
    asm volatile("ldmatrix.sync.aligned.m8n8.x4.shared.b16 {%0,%1,%2,%3}, [%4];"
                 : "=r"(r0), "=r"(r1), "=r"(r2), "=r"(r3) : "r"(addr));
}
__device__ __forceinline__ void ldsm4t(uint32_t addr, uint32_t& r0, uint32_t& r1,
                                       uint32_t& r2, uint32_t& r3) {
    asm volatile("ldmatrix.sync.aligned.m8n8.x4.trans.shared.b16 {%0,%1,%2,%3}, [%4];"
                 : "=r"(r0), "=r"(r1), "=r"(r2), "=r"(r3) : "r"(addr));
}
// fp16 MMA, fp32 accumulate: m16n8k16
__device__ __forceinline__ void mma_f16(float c[4], uint32_t a0, uint32_t a1,
                                        uint32_t a2, uint32_t a3,
                                        uint32_t b0, uint32_t b1) {
    asm volatile(
        "mma.sync.aligned.m16n8k16.row.col.f32.f16.f16.f32 "
        "{%0,%1,%2,%3}, {%4,%5,%6,%7}, {%8,%9}, {%0,%1,%2,%3};"
        : "+f"(c[0]), "+f"(c[1]), "+f"(c[2]), "+f"(c[3])
        : "r"(a0), "r"(a1), "r"(a2), "r"(a3), "r"(b0), "r"(b1));
}
__device__ __forceinline__ uint32_t sw128(uint32_t bo) {
    return bo ^ ((bo >> 3) & 0x70);
}

// ---------------------------------------------------------------------------
// fp16 mma.sync GEMM: 128x128 CTA tile, BK=64, 4 warps, warp 64x64,
// 128 threads, 2 CTAs/SM.
// MODE 0: NT, +bias, write C fp16                          (GEMM1)
// MODE 2: NN (B=[K,N] row-major, ldmatrix.trans), *alpha, fp32 out (GEMM3)
// MODE 3: NT, *alpha, fp32, SYMMETRIC triangular + mirror  (GEMM2)
// ---------------------------------------------------------------------------
#define STG     3
#define A_TB    16384                    // 128 rows x 128B
#define SB_OFF  (STG * A_TB)             // 49152
#define B_TB_NT 16384
#define B_PITCH 272                      // NN: 64 rows x 272B (17 granules, odd)
#define B_TB_NN (64 * B_PITCH)           // 17408
#define DSMEM_NT (SB_OFF + STG * B_TB_NT + 1024)
#define DSMEM_NN (SB_OFF + STG * B_TB_NN + 1024)
#define TPITCH  132                      // transpose staging pitch (floats)

template <int MODE>
__global__ __launch_bounds__(128, 2)
void tc_gemm(const __half* __restrict__ Ag, const __half* __restrict__ Bg,
             const float* __restrict__ bias,
             float* __restrict__ Cg,            // fp32 out (MODE 2,3)
             __half* __restrict__ Ch,           // fp16 out (MODE 0)
             int N, int K, float alpha,
             size_t strA, size_t strB, size_t strC)
{
    constexpr int BSB = (MODE == 2) ? B_TB_NN : B_TB_NT;

    extern __shared__ char dsm[];
    const uint32_t sb = (smem_u32(dsm) + 1023u) & ~1023u;

    Ag += (size_t)blockIdx.z * strA;
    Bg += (size_t)blockIdx.z * strB;
    if (MODE != 0) Cg += (size_t)blockIdx.z * strC;

    const int tid  = threadIdx.x;
    const int lane = tid & 31;
    const int wid  = tid >> 5;           // 0..3
    const int wm0  = (wid & 1) * 64;     // warp m offset
    const int wn0  = (wid >> 1) * 64;    // warp n offset

    int row0, col0;
    if (MODE == 3) {
        const int t = blockIdx.x;
        int r = (int)((sqrtf(8.0f * (float)t + 1.0f) - 1.0f) * 0.5f);
        while ((r + 1) * (r + 2) / 2 <= t) r++;
        while (r * (r + 1) / 2 > t)        r--;
        const int cc = t - r * (r + 1) / 2;
        row0 = r  * 128;
        col0 = cc * 128;
    } else {
        row0 = blockIdx.y * 128;
        col0 = blockIdx.x * 128;
    }

    const int NCH = K >> 6;              // BK = 64 fp16
    const int q = lane >> 2;             // 0..7 (fragment row)
    const int s = lane & 3;              // 0..3

    // ldmatrix per-lane constants (NT path)
    const uint32_t tb   = ((lane >> 3) & 1) << 3;   // +8 rows for odd tiles
    const uint32_t th16 = ((lane >> 4) & 1) << 4;   // +16B => k 8..15
    const uint32_t xr   = (uint32_t)(lane & 7) << 4;
    uint32_t roffA[4], roffB[4];
#pragma unroll
    for (int t4 = 0; t4 < 4; t4++)
        roffA[t4] = (uint32_t)(wm0 + (t4 << 4) + tb + (lane & 7)) << 7;
    if (MODE != 2) {
#pragma unroll
        for (int t4 = 0; t4 < 4; t4++)
            roffB[t4] = (uint32_t)(wn0 + (t4 << 4) + tb + (lane & 7)) << 7;
    } else {
        // NN trans: lanes 0-7 -> (k0-7, n-lo), 8-15 -> (k0-7, n-hi),
        //           16-23 -> (k8-15, n-lo), 24-31 -> (k8-15, n-hi)
        const uint32_t krow = (uint32_t)(lane & 7) + (((uint32_t)lane >> 4) << 3);
        const uint32_t nhi  = (((uint32_t)lane >> 3) & 1) << 4;  // +8 cols = 16B
#pragma unroll
        for (int p = 0; p < 4; p++)
            roffB[p] = krow * B_PITCH + (uint32_t)(wn0 + (p << 4)) * 2 + nhi;
    }

    float acc[4][8][4];
#pragma unroll
    for (int i = 0; i < 4; i++)
#pragma unroll
        for (int j = 0; j < 8; j++)
#pragma unroll
            for (int r = 0; r < 4; r++) acc[i][j][r] = 0.f;

    auto issue = [&](int ch, int st) {
        const int k0 = ch << 6;                    // fp16 elements
#pragma unroll
        for (int i = 0; i < 16; i++) {
            int g   = tid + (i << 7);              // 0..2047
            int isB = g >> 10;
            int gl  = g & 1023;
            const __half* src;
            uint32_t dst;
            if (!isB) {                            // A: 128 rows x 8 granules
                int r  = gl >> 3;
                int gg = gl & 7;
                src = Ag + (size_t)(row0 + r) * K + k0 + (gg << 3);
                dst = sb + st * A_TB + sw128((r << 7) + (gg << 4));
            } else if (MODE != 2) {                // B NT: [n][k]
                int r  = gl >> 3;
                int gg = gl & 7;
                src = Bg + (size_t)(col0 + r) * K + k0 + (gg << 3);
                dst = sb + SB_OFF + st * BSB + sw128((r << 7) + (gg << 4));
            } else {                               // B NN: [k][n], 64 rows x 16 gran
                int kr = gl >> 4;
                int gg = gl & 15;
                src = Bg + (size_t)(k0 + kr) * N + col0 + (gg << 3);
                dst = sb + SB_OFF + st * BSB + kr * B_PITCH + (gg << 4);
            }
            asm volatile("cp.async.cg.shared.global [%0], [%1], 16;"
                         :: "r"(dst), "l"(src) : "memory");
        }
        asm volatile("cp.async.commit_group;" ::: "memory");
    };

    auto step = [&](int ch, const int st) {
        asm volatile("cp.async.wait_group 1;" ::: "memory");
        __syncthreads();
        if (ch + 2 < NCH) issue(ch + 2, (st + 2) % STG);
        else asm volatile("cp.async.commit_group;" ::: "memory");

        const uint32_t ab = sb + st * A_TB;
        const uint32_t bb = sb + SB_OFF + st * BSB;

#pragma unroll
        for (int ks = 0; ks < 4; ks++) {           // 4 x k16 = BK 64
            const uint32_t kx = (((uint32_t)ks << 5) + th16) ^ xr;
            uint32_t af[16], bf[16];
            if (MODE != 2) {
#pragma unroll
                for (int tp = 0; tp < 4; tp++)
                    ldsm4(bb + roffB[tp] + kx,
                          bf[(tp * 2) * 2], bf[(tp * 2 + 1) * 2],
                          bf[(tp * 2) * 2 + 1], bf[(tp * 2 + 1) * 2 + 1]);
            } else {
                const uint32_t kxn = (uint32_t)(ks << 4) * B_PITCH;  // +16 k rows
#pragma unroll
                for (int tp = 0; tp < 4; tp++)
                    ldsm4t(bb + roffB[tp] + kxn,
                           bf[(tp * 2) * 2], bf[(tp * 2 + 1) * 2],
                           bf[(tp * 2) * 2 + 1], bf[(tp * 2 + 1) * 2 + 1]);
            }
#pragma unroll
            for (int tm = 0; tm < 4; tm++)
                ldsm4(ab + roffA[tm] + kx,
                      af[tm * 4], af[tm * 4 + 1], af[tm * 4 + 2], af[tm * 4 + 3]);
#pragma unroll
            for (int tm = 0; tm < 4; tm++)
#pragma unroll
                for (int tn = 0; tn < 8; tn++)
                    mma_f16(acc[tm][tn], af[tm * 4], af[tm * 4 + 1],
                            af[tm * 4 + 2], af[tm * 4 + 3],
                            bf[tn * 2], bf[tn * 2 + 1]);
        }
    };

    issue(0, 0);
    issue(1, 1);

    int ch = 0;
#pragma unroll 1
    for (; ch + 3 <= NCH; ch += 3) {
        step(ch,     0);
        step(ch + 1, 1);
        step(ch + 2, 2);
    }
    if (ch < NCH) { step(ch, 0); ch++; }
    if (ch < NCH) { step(ch, 1); }

    // -------- epilogue --------
    if (MODE == 0) {
        // bias add, round to fp16, write C only
#pragma unroll
        for (int tm = 0; tm < 4; tm++) {
            const size_t r_lo = (size_t)row0 + wm0 + (tm << 4) + q;
#pragma unroll
            for (int tn = 0; tn < 8; tn++) {
                const int col = col0 + wn0 + (tn << 3) + (s << 1);
                const float b0 = __ldg(bias + col), b1 = __ldg(bias + col + 1);
                __half h0 = __float2half_rn(acc[tm][tn][0] + b0);
                __half h1 = __float2half_rn(acc[tm][tn][1] + b1);
                __half h2 = __float2half_rn(acc[tm][tn][2] + b0);
                __half h3 = __float2half_rn(acc[tm][tn][3] + b1);
                *reinterpret_cast<__half2*>(Ch + r_lo * N + col) =
                    __halves2half2(h0, h1);
                *reinterpret_cast<__half2*>(Ch + (r_lo + 8) * N + col) =
                    __halves2half2(h2, h3);
            }
        }
    } else if (MODE == 2) {
#pragma unroll
        for (int tm = 0; tm < 4; tm++) {
            const size_t r_lo = (size_t)row0 + wm0 + (tm << 4) + q;
#pragma unroll
            for (int tn = 0; tn < 8; tn++) {
                const int col = col0 + wn0 + (tn << 3) + (s << 1);
                *reinterpret_cast<float2*>(Cg + r_lo * N + col) =
                    make_float2(acc[tm][tn][0] * alpha, acc[tm][tn][1] * alpha);
                *reinterpret_cast<float2*>(Cg + (r_lo + 8) * N + col) =
                    make_float2(acc[tm][tn][2] * alpha, acc[tm][tn][3] * alpha);
            }
        }
    } else {  // MODE 3
        const bool diag = (row0 == col0);
#pragma unroll
        for (int tm = 0; tm < 4; tm++) {
            const size_t r_lo = (size_t)row0 + wm0 + (tm << 4) + q;
#pragma unroll
            for (int tn = 0; tn < 8; tn++) {
                const int col = col0 + wn0 + (tn << 3) + (s << 1);
                float v0 = acc[tm][tn][0] * alpha, v1 = acc[tm][tn][1] * alpha;
                float v2 = acc[tm][tn][2] * alpha, v3 = acc[tm][tn][3] * alpha;
                acc[tm][tn][0] = v0; acc[tm][tn][1] = v1;
                acc[tm][tn][2] = v2; acc[tm][tn][3] = v3;
                *reinterpret_cast<float2*>(Cg + r_lo * N + col)       = make_float2(v0, v1);
                *reinterpret_cast<float2*>(Cg + (r_lo + 8) * N + col) = make_float2(v2, v3);
            }
        }
        if (!diag) {
            asm volatile("cp.async.wait_group 0;" ::: "memory");
            __syncthreads();
#pragma unroll
            for (int tm = 0; tm < 4; tm++) {
                const int m = wm0 + (tm << 4) + q;
#pragma unroll
                for (int tn = 0; tn < 8; tn++) {
                    const int n = wn0 + (tn << 3) + (s << 1);
                    sts_f(sb + (uint32_t)(n       * TPITCH + m)     * 4, acc[tm][tn][0]);
                    sts_f(sb + (uint32_t)((n + 1) * TPITCH + m)     * 4, acc[tm][tn][1]);
                    sts_f(sb + (uint32_t)(n       * TPITCH + m + 8) * 4, acc[tm][tn][2]);
                    sts_f(sb + (uint32_t)((n + 1) * TPITCH + m + 8) * 4, acc[tm][tn][3]);
                }
            }
            __syncthreads();
            float* dstrow = Cg + (size_t)(col0 + tid) * N + row0;
            const uint32_t srow = sb + (uint32_t)(tid * TPITCH) * 4;
#pragma unroll
            for (int j = 0; j < 128; j += 4) {
                float4 v = lds_f4(srow + j * 4);
                *reinterpret_cast<float4*>(dstrow + j) = v;
            }
        }
    }
}

// ---------------------------------------------------------------------------
// prepass: fp32 -> fp16 (RNE), embd and W in ONE launch
__global__ __launch_bounds__(256)
void round_h2(const float4* __restrict__ inE, __half2* __restrict__ outE, int n4e,
              const float4* __restrict__ inW, __half2* __restrict__ outW, int n4w)
{
    int i = blockIdx.x * 256 + threadIdx.x;
    if (i < n4e) {
        float4 v = inE[i];
        outE[2 * i]     = __floats2half2_rn(v.x, v.y);
        outE[2 * i + 1] = __floats2half2_rn(v.z, v.w);
    } else {
        int j = i - n4e;
        if (j < n4w) {
            float4 v = inW[j];
            outW[2 * j]     = __floats2half2_rn(v.x, v.y);
            outW[2 * j + 1] = __floats2half2_rn(v.z, v.w);
        }
    }
}

// row softmax over 2048 cols (fp32 logits); writes probs*1024 as fp16
__global__ __launch_bounds__(256)
void softmax_kernel(const float* __restrict__ S, __half* __restrict__ P)
{
    const float4* p4 = reinterpret_cast<const float4*>(S + (size_t)blockIdx.x * SEQ);
    __half2* q2 = reinterpret_cast<__half2*>(P + (size_t)blockIdx.x * SEQ);
    const int tid  = threadIdx.x;
    const int lane = tid & 31;
    const int wid  = tid >> 5;
    __shared__ float red[8];

    float4 u0 = p4[tid], u1 = p4[tid + 256];
    float m = fmaxf(fmaxf(fmaxf(u0.x, u0.y), fmaxf(u0.z, u0.w)),
                    fmaxf(fmaxf(u1.x, u1.y), fmaxf(u1.z, u1.w)));
#pragma unroll
    for (int o = 16; o > 0; o >>= 1)
        m = fmaxf(m, __shfl_xor_sync(0xffffffffu, m, o));
    if (lane == 0) red[wid] = m;
    __syncthreads();
    float bm = red[0];
#pragma unroll
    for (int i = 1; i < 8; i++) bm = fmaxf(bm, red[i]);
    __syncthreads();

    u0.x = __expf(u0.x - bm); u0.y = __expf(u0.y - bm);
    u0.z = __expf(u0.z - bm); u0.w = __expf(u0.w - bm);
    u1.x = __expf(u1.x - bm); u1.y = __expf(u1.y - bm);
    u1.z = __expf(u1.z - bm); u1.w = __expf(u1.w - bm);
    float sum = (u0.x + u0.y) + (u0.z + u0.w) + (u1.x + u1.y) + (u1.z + u1.w);
#pragma unroll
    for (int o = 16; o > 0; o >>= 1)
        sum += __shfl_xor_sync(0xffffffffu, sum, o);
    if (lane == 0) red[wid] = sum;
    __syncthreads();
    float total = 0.f;
#pragma unroll
    for (int i = 0; i < 8; i++) total += red[i];
    const float k = 1024.f / total;       // scale by 1024 into fp16 normal range

    q2[2 * tid]           = __floats2half2_rn(u0.x * k, u0.y * k);
    q2[2 * tid + 1]       = __floats2half2_rn(u0.z * k, u0.w * k);
    q2[512 + 2 * tid]     = __floats2half2_rn(u1.x * k, u1.y * k);
    q2[512 + 2 * tid + 1] = __floats2half2_rn(u1.z * k, u1.w * k);
}

// ---------------------------------------------------------------------------
extern "C" void kernel_launch(void* const* d_in, const int* in_sizes, int n_in,
                              void* d_out, int out_size)
{
    const float* embd = (const float*)d_in[0];   // [8,2048,1024]
    const float* W    = (const float*)d_in[1];   // [1024,1024]
    const float* bias = (const float*)d_in[2];   // [1024]
    float* out = (float*)d_out;                  // [8,2048,1024]

    __half *et, *wt, *c, *p;
    float *s;
    cudaGetSymbolAddress((void**)&et, g_et);
    cudaGetSymbolAddress((void**)&wt, g_wt);
    cudaGetSymbolAddress((void**)&c,  g_c);
    cudaGetSymbolAddress((void**)&s,  g_s);
    cudaGetSymbolAddress((void**)&p,  g_p);

    cudaFuncSetAttribute(tc_gemm<0>, cudaFuncAttributeMaxDynamicSharedMemorySize, DSMEM_NT);
    cudaFuncSetAttribute(tc_gemm<2>, cudaFuncAttributeMaxDynamicSharedMemorySize, DSMEM_NN);
    cudaFuncSetAttribute(tc_gemm<3>, cudaFuncAttributeMaxDynamicSharedMemorySize, DSMEM_NT);

    const float scale = 0.03125f;  // 1/sqrt(1024)

    // prepass: round inputs to fp16 (single launch)
    {
        int n4e = BATCH * SEQ * EMBD / 4;
        int n4w = OUTD * EMBD / 4;
        int total = n4e + n4w;
        round_h2<<<(total + 255) / 256, 256>>>((const float4*)embd, (__half2*)et, n4e,
                                               (const float4*)W, (__half2*)wt, n4w);
    }

    // 1) c = embd @ W^T + b  (NT), writes c fp16 only (no transpose copy)
    {
        dim3 grid(OUTD / 128, (BATCH * SEQ) / 128, 1);
        tc_gemm<0><<<grid, 128, DSMEM_NT>>>(et, wt, bias, nullptr, c,
                                            OUTD, EMBD, 1.0f, 0, 0, 0);
    }
    // 2) s = (c @ c^T) * scale per batch — symmetric: 136 triangular tiles
    {
        dim3 grid(136, 1, BATCH);
        tc_gemm<3><<<grid, 128, DSMEM_NT>>>(c, c, nullptr, s, nullptr,
                                            SEQ, OUTD, scale,
                                            (size_t)SEQ * OUTD, (size_t)SEQ * OUTD,
                                            (size_t)SEQ * SEQ);
    }
    // 3) softmax rows -> probs*1024 in fp16
    softmax_kernel<<<BATCH * SEQ, 256>>>(s, p);

    // 4) out = (P/1024) @ c  (NN: B = c as [K=2048, N=1024] row-major)
    {
        dim3 grid(OUTD / 128, SEQ / 128, BATCH);
        tc_gemm<2><<<grid, 128, DSMEM_NN>>>(p, c, nullptr, out, nullptr,
                                            OUTD, SEQ, 1.0f / 1024.f,
                                            (size_t)SEQ * SEQ, (size_t)SEQ * OUTD,
                                            (size_t)SEQ * OUTD);
    }
}

// round 17
// speedup vs baseline: 1.5304x; 1.0135x over previous
#include <cuda_runtime.h>
#include <cuda_fp16.h>
#include <cstdint>

#define BATCH 8
#define SEQ   2048
#define EMBD  1024
#define OUTD  1024

// Scratch (device globals; allocations are forbidden)
__device__ __align__(256) __half g_et[(size_t)BATCH * SEQ * EMBD];  // fp16 embd 32MB
__device__ __align__(256) __half g_wt[(size_t)OUTD * EMBD];         // fp16 W     2MB
__device__ __align__(256) __half g_c [(size_t)BATCH * SEQ * OUTD];  // c fp16    32MB
__device__ __align__(256) float  g_s [(size_t)BATCH * SEQ * SEQ];   // logits   128MB
__device__ __align__(256) __half g_p [(size_t)BATCH * SEQ * SEQ];   // probs*1024 64MB

// ---------------------------------------------------------------------------
__device__ __forceinline__ uint32_t smem_u32(const void* p) {
    uint32_t a;
    asm("{ .reg .u64 t; cvta.to.shared.u64 t, %1; cvt.u32.u64 %0, t; }"
        : "=r"(a) : "l"(p));
    return a;
}
__device__ __forceinline__ void sts_f(uint32_t a, float v) {
    asm volatile("st.shared.b32 [%0], %1;" :: "r"(a), "f"(v) : "memory");
}
__device__ __forceinline__ float4 lds_f4(uint32_t a) {
    float4 v;
    asm volatile("ld.shared.v4.f32 {%0,%1,%2,%3}, [%4];"
                 : "=f"(v.x), "=f"(v.y), "=f"(v.z), "=f"(v.w) : "r"(a));
    return v;
}
__device__ __forceinline__ void ldsm4(uint32_t addr, uint32_t& r0, uint32_t& r1,
                                      uint32_t& r2, uint32_t& r3) {
    asm volatile("ldmatrix.sync.aligned.m8n8.x4.shared.b16 {%0,%1,%2,%3}, [%4];"
                 : "=r"(r0), "=r"(r1), "=r"(r2), "=r"(r3) : "r"(addr));
}
__device__ __forceinline__ void ldsm4t(uint32_t addr, uint32_t& r0, uint32_t& r1,
                                       uint32_t& r2, uint32_t& r3) {
    asm volatile("ldmatrix.sync.aligned.m8n8.x4.trans.shared.b16 {%0,%1,%2,%3}, [%4];"
                 : "=r"(r0), "=r"(r1), "=r"(r2), "=r"(r3) : "r"(addr));
}
// fp16 MMA, fp32 accumulate: m16n8k16
__device__ __forceinline__ void mma_f16(float c[4], uint32_t a0, uint32_t a1,
                                        uint32_t a2, uint32_t a3,
                                        uint32_t b0, uint32_t b1) {
    asm volatile(
        "mma.sync.aligned.m16n8k16.row.col.f32.f16.f16.f32 "
        "{%0,%1,%2,%3}, {%4,%5,%6,%7}, {%8,%9}, {%0,%1,%2,%3};"
        : "+f"(c[0]), "+f"(c[1]), "+f"(c[2]), "+f"(c[3])
        : "r"(a0), "r"(a1), "r"(a2), "r"(a3), "r"(b0), "r"(b1));
}
__device__ __forceinline__ uint32_t sw128(uint32_t bo) {
    return bo ^ ((bo >> 3) & 0x70);
}

// ---------------------------------------------------------------------------
// fp16 mma.sync GEMM: 128x128 CTA tile, BK=64, 4 warps, warp 64x64,
// 128 threads, 2 CTAs/SM.
// MODE 0: NT, +bias, write C fp16                          (GEMM1)
// MODE 2: NN (B=[K,N] row-major, ldmatrix.trans), *alpha, fp32 out (GEMM3)
// MODE 3: NT, *alpha, fp32, SYMMETRIC triangular + mirror  (GEMM2)
// ---------------------------------------------------------------------------
#define STG     3
#define A_TB    16384                    // 128 rows x 128B
#define SB_OFF  (STG * A_TB)             // 49152
#define B_TB_NT 16384
#define B_PITCH 272                      // NN: 64 rows x 272B (17 granules, odd)
#define B_TB_NN (64 * B_PITCH)           // 17408
#define DSMEM_NT (SB_OFF + STG * B_TB_NT + 1024)
#define DSMEM_NN (SB_OFF + STG * B_TB_NN + 1024)
#define TPITCH  132                      // transpose staging pitch (floats)

template <int MODE>
__global__ __launch_bounds__(128, 2)
void tc_gemm(const __half* __restrict__ Ag, const __half* __restrict__ Bg,
             const float* __restrict__ bias,
             float* __restrict__ Cg,            // fp32 out (MODE 2,3)
             __half* __restrict__ Ch,           // fp16 out (MODE 0)
             int N, int K, float alpha,
             size_t strA, size_t strB, size_t strC)
{
    constexpr int BSB = (MODE == 2) ? B_TB_NN : B_TB_NT;

    extern __shared__ char dsm[];
    const uint32_t sb = (smem_u32(dsm) + 1023u) & ~1023u;

    Ag += (size_t)blockIdx.z * strA;
    Bg += (size_t)blockIdx.z * strB;
    if (MODE != 0) Cg += (size_t)blockIdx.z * strC;

    const int tid  = threadIdx.x;
    const int lane = tid & 31;
    const int wid  = tid >> 5;           // 0..3
    const int wm0  = (wid & 1) * 64;     // warp m offset
    const int wn0  = (wid >> 1) * 64;    // warp n offset

    int row0, col0;
    if (MODE == 3) {
        const int t = blockIdx.x;
        int r = (int)((sqrtf(8.0f * (float)t + 1.0f) - 1.0f) * 0.5f);
        while ((r + 1) * (r + 2) / 2 <= t) r++;
        while (r * (r + 1) / 2 > t)        r--;
        const int cc = t - r * (r + 1) / 2;
        row0 = r  * 128;
        col0 = cc * 128;
    } else {
        row0 = blockIdx.y * 128;
        col0 = blockIdx.x * 128;
    }

    const int NCH = K >> 6;              // BK = 64 fp16
    const int q = lane >> 2;             // 0..7 (fragment row)
    const int s = lane & 3;              // 0..3

    // ldmatrix per-lane constants (NT path)
    const uint32_t tb   = ((lane >> 3) & 1) << 3;   // +8 rows for odd tiles
    const uint32_t th16 = ((lane >> 4) & 1) << 4;   // +16B => k 8..15
    const uint32_t xr   = (uint32_t)(lane & 7) << 4;
    uint32_t roffA[4], roffB[4];
#pragma unroll
    for (int t4 = 0; t4 < 4; t4++)
        roffA[t4] = (uint32_t)(wm0 + (t4 << 4) + tb + (lane & 7)) << 7;
    if (MODE != 2) {
#pragma unroll
        for (int t4 = 0; t4 < 4; t4++)
            roffB[t4] = (uint32_t)(wn0 + (t4 << 4) + tb + (lane & 7)) << 7;
    } else {
        // NN trans: lanes 0-7 -> (k0-7, n-lo), 8-15 -> (k0-7, n-hi),
        //           16-23 -> (k8-15, n-lo), 24-31 -> (k8-15, n-hi)
        const uint32_t krow = (uint32_t)(lane & 7) + (((uint32_t)lane >> 4) << 3);
        const uint32_t nhi  = (((uint32_t)lane >> 3) & 1) << 4;  // +8 cols = 16B
#pragma unroll
        for (int p = 0; p < 4; p++)
            roffB[p] = krow * B_PITCH + (uint32_t)(wn0 + (p << 4)) * 2 + nhi;
    }

    float acc[4][8][4];
#pragma unroll
    for (int i = 0; i < 4; i++)
#pragma unroll
        for (int j = 0; j < 8; j++)
#pragma unroll
            for (int r = 0; r < 4; r++) acc[i][j][r] = 0.f;

    auto issue = [&](int ch, int st) {
        const int k0 = ch << 6;                    // fp16 elements
#pragma unroll
        for (int i = 0; i < 16; i++) {
            int g   = tid + (i << 7);              // 0..2047
            int isB = g >> 10;
            int gl  = g & 1023;
            const __half* src;
            uint32_t dst;
            if (!isB) {                            // A: 128 rows x 8 granules
                int r  = gl >> 3;
                int gg = gl & 7;
                src = Ag + (size_t)(row0 + r) * K + k0 + (gg << 3);
                dst = sb + st * A_TB + sw128((r << 7) + (gg << 4));
            } else if (MODE != 2) {                // B NT: [n][k]
                int r  = gl >> 3;
                int gg = gl & 7;
                src = Bg + (size_t)(col0 + r) * K + k0 + (gg << 3);
                dst = sb + SB_OFF + st * BSB + sw128((r << 7) + (gg << 4));
            } else {                               // B NN: [k][n], 64 rows x 16 gran
                int kr = gl >> 4;
                int gg = gl & 15;
                src = Bg + (size_t)(k0 + kr) * N + col0 + (gg << 3);
                dst = sb + SB_OFF + st * BSB + kr * B_PITCH + (gg << 4);
            }
            asm volatile("cp.async.cg.shared.global [%0], [%1], 16;"
                         :: "r"(dst), "l"(src) : "memory");
        }
        asm volatile("cp.async.commit_group;" ::: "memory");
    };

    auto step = [&](int ch, const int st) {
        asm volatile("cp.async.wait_group 1;" ::: "memory");
        __syncthreads();
        if (ch + 2 < NCH) issue(ch + 2, (st + 2) % STG);
        else asm volatile("cp.async.commit_group;" ::: "memory");

        const uint32_t ab = sb + st * A_TB;
        const uint32_t bb = sb + SB_OFF + st * BSB;

#pragma unroll
        for (int ks = 0; ks < 4; ks++) {           // 4 x k16 = BK 64
            const uint32_t kx = (((uint32_t)ks << 5) + th16) ^ xr;
            uint32_t af[16], bf[16];
            if (MODE != 2) {
#pragma unroll
                for (int tp = 0; tp < 4; tp++)
                    ldsm4(bb + roffB[tp] + kx,
                          bf[(tp * 2) * 2], bf[(tp * 2 + 1) * 2],
                          bf[(tp * 2) * 2 + 1], bf[(tp * 2 + 1) * 2 + 1]);
            } else {
                const uint32_t kxn = (uint32_t)(ks << 4) * B_PITCH;  // +16 k rows
#pragma unroll
                for (int tp = 0; tp < 4; tp++)
                    ldsm4t(bb + roffB[tp] + kxn,
                           bf[(tp * 2) * 2], bf[(tp * 2 + 1) * 2],
                           bf[(tp * 2) * 2 + 1], bf[(tp * 2 + 1) * 2 + 1]);
            }
#pragma unroll
            for (int tm = 0; tm < 4; tm++)
                ldsm4(ab + roffA[tm] + kx,
                      af[tm * 4], af[tm * 4 + 1], af[tm * 4 + 2], af[tm * 4 + 3]);
#pragma unroll
            for (int tm = 0; tm < 4; tm++)
#pragma unroll
                for (int tn = 0; tn < 8; tn++)
                    mma_f16(acc[tm][tn], af[tm * 4], af[tm * 4 + 1],
                            af[tm * 4 + 2], af[tm * 4 + 3],
                            bf[tn * 2], bf[tn * 2 + 1]);
        }
    };

    issue(0, 0);
    issue(1, 1);

    int ch = 0;
#pragma unroll 1
    for (; ch + 3 <= NCH; ch += 3) {
        step(ch,     0);
        step(ch + 1, 1);
        step(ch + 2, 2);
    }
    if (ch < NCH) { step(ch, 0); ch++; }
    if (ch < NCH) { step(ch, 1); }

    // -------- epilogue --------
    if (MODE == 0) {
        // bias add, round to fp16, write C only
#pragma unroll
        for (int tm = 0; tm < 4; tm++) {
            const size_t r_lo = (size_t)row0 + wm0 + (tm << 4) + q;
#pragma unroll
            for (int tn = 0; tn < 8; tn++) {
                const int col = col0 + wn0 + (tn << 3) + (s << 1);
                const float b0 = __ldg(bias + col), b1 = __ldg(bias + col + 1);
                __half h0 = __float2half_rn(acc[tm][tn][0] + b0);
                __half h1 = __float2half_rn(acc[tm][tn][1] + b1);
                __half h2 = __float2half_rn(acc[tm][tn][2] + b0);
                __half h3 = __float2half_rn(acc[tm][tn][3] + b1);
                *reinterpret_cast<__half2*>(Ch + r_lo * N + col) =
                    __halves2half2(h0, h1);
                *reinterpret_cast<__half2*>(Ch + (r_lo + 8) * N + col) =
                    __halves2half2(h2, h3);
            }
        }
    } else if (MODE == 2) {
#pragma unroll
        for (int tm = 0; tm < 4; tm++) {
            const size_t r_lo = (size_t)row0 + wm0 + (tm << 4) + q;
#pragma unroll
            for (int tn = 0; tn < 8; tn++) {
                const int col = col0 + wn0 + (tn << 3) + (s << 1);
                *reinterpret_cast<float2*>(Cg + r_lo * N + col) =
                    make_float2(acc[tm][tn][0] * alpha, acc[tm][tn][1] * alpha);
                *reinterpret_cast<float2*>(Cg + (r_lo + 8) * N + col) =
                    make_float2(acc[tm][tn][2] * alpha, acc[tm][tn][3] * alpha);
            }
        }
    } else {  // MODE 3
        const bool diag = (row0 == col0);
#pragma unroll
        for (int tm = 0; tm < 4; tm++) {
            const size_t r_lo = (size_t)row0 + wm0 + (tm << 4) + q;
#pragma unroll
            for (int tn = 0; tn < 8; tn++) {
                const int col = col0 + wn0 + (tn << 3) + (s << 1);
                float v0 = acc[tm][tn][0] * alpha, v1 = acc[tm][tn][1] * alpha;
                float v2 = acc[tm][tn][2] * alpha, v3 = acc[tm][tn][3] * alpha;
                acc[tm][tn][0] = v0; acc[tm][tn][1] = v1;
                acc[tm][tn][2] = v2; acc[tm][tn][3] = v3;
                *reinterpret_cast<float2*>(Cg + r_lo * N + col)       = make_float2(v0, v1);
                *reinterpret_cast<float2*>(Cg + (r_lo + 8) * N + col) = make_float2(v2, v3);
            }
        }
        if (!diag) {
            asm volatile("cp.async.wait_group 0;" ::: "memory");
            __syncthreads();
#pragma unroll
            for (int tm = 0; tm < 4; tm++) {
                const int m = wm0 + (tm << 4) + q;
#pragma unroll
                for (int tn = 0; tn < 8; tn++) {
                    const int n = wn0 + (tn << 3) + (s << 1);
                    sts_f(sb + (uint32_t)(n       * TPITCH + m)     * 4, acc[tm][tn][0]);
                    sts_f(sb + (uint32_t)((n + 1) * TPITCH + m)     * 4, acc[tm][tn][1]);
                    sts_f(sb + (uint32_t)(n       * TPITCH + m + 8) * 4, acc[tm][tn][2]);
                    sts_f(sb + (uint32_t)((n + 1) * TPITCH + m + 8) * 4, acc[tm][tn][3]);
                }
            }
            __syncthreads();
            float* dstrow = Cg + (size_t)(col0 + tid) * N + row0;
            const uint32_t srow = sb + (uint32_t)(tid * TPITCH) * 4;
#pragma unroll
            for (int j = 0; j < 128; j += 4) {
                float4 v = lds_f4(srow + j * 4);
                *reinterpret_cast<float4*>(dstrow + j) = v;
            }
        }
    }
}

// ---------------------------------------------------------------------------
// prepass: fp32 -> fp16 (RNE), embd and W in ONE launch
__global__ __launch_bounds__(256)
void round_h2(const float4* __restrict__ inE, __half2* __restrict__ outE, int n4e,
              const float4* __restrict__ inW, __half2* __restrict__ outW, int n4w)
{
    int i = blockIdx.x * 256 + threadIdx.x;
    if (i < n4e) {
        float4 v = inE[i];
        outE[2 * i]     = __floats2half2_rn(v.x, v.y);
        outE[2 * i + 1] = __floats2half2_rn(v.z, v.w);
    } else {
        int j = i - n4e;
        if (j < n4w) {
            float4 v = inW[j];
            outW[2 * j]     = __floats2half2_rn(v.x, v.y);
            outW[2 * j + 1] = __floats2half2_rn(v.z, v.w);
        }
    }
}

// row softmax over 2048 cols (fp32 logits); 128 threads/row, MLP=4
// (4 independent float4 loads issued up front); probs*1024 as fp16
__global__ __launch_bounds__(128)
void softmax_kernel(const float* __restrict__ S, __half* __restrict__ P)
{
    const float4* p4 = reinterpret_cast<const float4*>(S + (size_t)blockIdx.x * SEQ);
    __half2* q2 = reinterpret_cast<__half2*>(P + (size_t)blockIdx.x * SEQ);
    const int tid  = threadIdx.x;
    const int lane = tid & 31;
    const int wid  = tid >> 5;            // 0..3
    __shared__ float red[4];

    // 4 front-batched float4 loads per thread (MLP=4): 128 thr x 16 = 2048
    float4 u0 = p4[tid];
    float4 u1 = p4[tid + 128];
    float4 u2 = p4[tid + 256];
    float4 u3 = p4[tid + 384];

    float m = fmaxf(fmaxf(fmaxf(u0.x, u0.y), fmaxf(u0.z, u0.w)),
                    fmaxf(fmaxf(u1.x, u1.y), fmaxf(u1.z, u1.w)));
    m = fmaxf(m, fmaxf(fmaxf(fmaxf(u2.x, u2.y), fmaxf(u2.z, u2.w)),
                       fmaxf(fmaxf(u3.x, u3.y), fmaxf(u3.z, u3.w))));
#pragma unroll
    for (int o = 16; o > 0; o >>= 1)
        m = fmaxf(m, __shfl_xor_sync(0xffffffffu, m, o));
    if (lane == 0) red[wid] = m;
    __syncthreads();
    float bm = fmaxf(fmaxf(red[0], red[1]), fmaxf(red[2], red[3]));
    __syncthreads();

    u0.x = __expf(u0.x - bm); u0.y = __expf(u0.y - bm);
    u0.z = __expf(u0.z - bm); u0.w = __expf(u0.w - bm);
    u1.x = __expf(u1.x - bm); u1.y = __expf(u1.y - bm);
    u1.z = __expf(u1.z - bm); u1.w = __expf(u1.w - bm);
    u2.x = __expf(u2.x - bm); u2.y = __expf(u2.y - bm);
    u2.z = __expf(u2.z - bm); u2.w = __expf(u2.w - bm);
    u3.x = __expf(u3.x - bm); u3.y = __expf(u3.y - bm);
    u3.z = __expf(u3.z - bm); u3.w = __expf(u3.w - bm);
    float sum = ((u0.x + u0.y) + (u0.z + u0.w)) + ((u1.x + u1.y) + (u1.z + u1.w))
              + ((u2.x + u2.y) + (u2.z + u2.w)) + ((u3.x + u3.y) + (u3.z + u3.w));
#pragma unroll
    for (int o = 16; o > 0; o >>= 1)
        sum += __shfl_xor_sync(0xffffffffu, sum, o);
    if (lane == 0) red[wid] = sum;
    __syncthreads();
    float total = (red[0] + red[1]) + (red[2] + red[3]);
    const float k = 1024.f / total;       // scale by 1024 into fp16 normal range

    q2[2 * tid]             = __floats2half2_rn(u0.x * k, u0.y * k);
    q2[2 * tid + 1]         = __floats2half2_rn(u0.z * k, u0.w * k);
    q2[2 * (tid + 128)]     = __floats2half2_rn(u1.x * k, u1.y * k);
    q2[2 * (tid + 128) + 1] = __floats2half2_rn(u1.z * k, u1.w * k);
    q2[2 * (tid + 256)]     = __floats2half2_rn(u2.x * k, u2.y * k);
    q2[2 * (tid + 256) + 1] = __floats2half2_rn(u2.z * k, u2.w * k);
    q2[2 * (tid + 384)]     = __floats2half2_rn(u3.x * k, u3.y * k);
    q2[2 * (tid + 384) + 1] = __floats2half2_rn(u3.z * k, u3.w * k);
}

// ---------------------------------------------------------------------------
extern "C" void kernel_launch(void* const* d_in, const int* in_sizes, int n_in,
                              void* d_out, int out_size)
{
    const float* embd = (const float*)d_in[0];   // [8,2048,1024]
    const float* W    = (const float*)d_in[1];   // [1024,1024]
    const float* bias = (const float*)d_in[2];   // [1024]
    float* out = (float*)d_out;                  // [8,2048,1024]

    __half *et, *wt, *c, *p;
    float *s;
    cudaGetSymbolAddress((void**)&et, g_et);
    cudaGetSymbolAddress((void**)&wt, g_wt);
    cudaGetSymbolAddress((void**)&c,  g_c);
    cudaGetSymbolAddress((void**)&s,  g_s);
    cudaGetSymbolAddress((void**)&p,  g_p);

    cudaFuncSetAttribute(tc_gemm<0>, cudaFuncAttributeMaxDynamicSharedMemorySize, DSMEM_NT);
    cudaFuncSetAttribute(tc_gemm<2>, cudaFuncAttributeMaxDynamicSharedMemorySize, DSMEM_NN);
    cudaFuncSetAttribute(tc_gemm<3>, cudaFuncAttributeMaxDynamicSharedMemorySize, DSMEM_NT);

    const float scale = 0.03125f;  // 1/sqrt(1024)

    // prepass: round inputs to fp16 (single launch)
    {
        int n4e = BATCH * SEQ * EMBD / 4;
        int n4w = OUTD * EMBD / 4;
        int total = n4e + n4w;
        round_h2<<<(total + 255) / 256, 256>>>((const float4*)embd, (__half2*)et, n4e,
                                               (const float4*)W, (__half2*)wt, n4w);
    }

    // 1) c = embd @ W^T + b  (NT), writes c fp16 only
    {
        dim3 grid(OUTD / 128, (BATCH * SEQ) / 128, 1);
        tc_gemm<0><<<grid, 128, DSMEM_NT>>>(et, wt, bias, nullptr, c,
                                            OUTD, EMBD, 1.0f, 0, 0, 0);
    }
    // 2) s = (c @ c^T) * scale per batch — symmetric: 136 triangular tiles
    {
        dim3 grid(136, 1, BATCH);
        tc_gemm<3><<<grid, 128, DSMEM_NT>>>(c, c, nullptr, s, nullptr,
                                            SEQ, OUTD, scale,
                                            (size_t)SEQ * OUTD, (size_t)SEQ * OUTD,
                                            (size_t)SEQ * SEQ);
    }
    // 3) softmax rows -> probs*1024 in fp16 (128 thr/row, MLP=4)
    softmax_kernel<<<BATCH * SEQ, 128>>>(s, p);

    // 4) out = (P/1024) @ c  (NN: B = c as [K=2048, N=1024] row-major)
    {
        dim3 grid(OUTD / 128, SEQ / 128, BATCH);
        tc_gemm<2><<<grid, 128, DSMEM_NN>>>(p, c, nullptr, out, nullptr,
                                            OUTD, SEQ, 1.0f / 1024.f,
                                            (size_t)SEQ * SEQ, (size_t)SEQ * OUTD,
                                            (size_t)SEQ * OUTD);
    }
}